// round 11
// baseline (speedup 1.0000x reference)
#include <cuda_runtime.h>
#include <cuda_fp16.h>
#include <cuda_pipeline.h>
#include <mma.h>
#include <math.h>

using namespace nvcuda;

// ---------------- problem constants ----------------
#define BATCH   4
#define SEQ     2048
#define DMODEL  768
#define DSTATE  16
#define DCONV   4
#define HEADDIM 64
#define DINNER  1536
#define NHEADS  24
#define CONVDIM 1568
#define DPROJ   3128
#define DPROJP  3328
#define NTOK    (BATCH*SEQ)
#define DFFN    3072

// ---------------- scratch (device globals; no allocation allowed) ----------------
__device__ __half h_proj[(size_t)2*NTOK*DPROJP];
__device__ __half h_conv[(size_t)2*NTOK*CONVDIM];
__device__ float  g_dt  [(size_t)2*NTOK*NHEADS];
__device__ float  g_dA  [(size_t)2*NTOK*NHEADS];
__device__ __half h_y   [(size_t)2*NTOK*DINNER];
__device__ __half h_yg  [(size_t)2*NTOK*DINNER];
__device__ float  g_h2  [(size_t)NTOK*DMODEL];

__device__ __half h_xn [(size_t)NTOK*DMODEL];
__device__ __half h_bi [(size_t)NTOK*DINNER];
__device__ __half h_ffn[(size_t)NTOK*DFFN];

// fp16 weight buffers
__device__ __half hw_in0 [(size_t)DMODEL*DPROJ];
__device__ __half hw_in1 [(size_t)DMODEL*DPROJ];
__device__ __half hw_out0[(size_t)DINNER*DMODEL];
__device__ __half hw_out1[(size_t)DINNER*DMODEL];
__device__ __half hw_f1  [(size_t)DINNER*DFFN];
__device__ __half hw_f2  [(size_t)DFFN*DMODEL];

// ---------------- helpers ----------------
__device__ __forceinline__ float gelu_exact(float x) {
    return 0.5f * x * (1.0f + erff(x * 0.70710678118654752f));
}
__device__ __forceinline__ float silu(float x) {
    return x / (1.0f + expf(-x));
}

__device__ float block_reduce_sum(float v) {
    __shared__ float sh[32];
    __shared__ float tot;
    int lane = threadIdx.x & 31, wid = threadIdx.x >> 5;
    #pragma unroll
    for (int m = 16; m >= 1; m >>= 1) v += __shfl_xor_sync(0xffffffffu, v, m);
    if (lane == 0) sh[wid] = v;
    __syncthreads();
    int nw = blockDim.x >> 5;
    v = (threadIdx.x < nw) ? sh[threadIdx.x] : 0.f;
    if (wid == 0) {
        #pragma unroll
        for (int m = 16; m >= 1; m >>= 1) v += __shfl_xor_sync(0xffffffffu, v, m);
        if (lane == 0) tot = v;
    }
    __syncthreads();
    return tot;
}

// ---------------- merged fp32 -> fp16 conversion for all 6 weights ----------------
#define N4_IN  (DMODEL*DPROJ/4)     // 600576
#define N4_OUT (DINNER*DMODEL/4)    // 294912
#define N4_F1  (DINNER*DFFN/4)      // 1179648
#define N4_F2  (DFFN*DMODEL/4)      // 589824
#define F2H_B0 (N4_IN)
#define F2H_B1 (2*N4_IN)
#define F2H_B2 (2*N4_IN + N4_OUT)
#define F2H_B3 (2*N4_IN + 2*N4_OUT)
#define F2H_B4 (2*N4_IN + 2*N4_OUT + N4_F1)
#define F2H_TOT (2*N4_IN + 2*N4_OUT + N4_F1 + N4_F2)

__global__ void f2h_all_kernel(
    const float* __restrict__ s0, const float* __restrict__ s1,
    const float* __restrict__ s2, const float* __restrict__ s3,
    const float* __restrict__ s4, const float* __restrict__ s5,
    __half* __restrict__ d0, __half* __restrict__ d1,
    __half* __restrict__ d2, __half* __restrict__ d3,
    __half* __restrict__ d4, __half* __restrict__ d5)
{
    int i = blockIdx.x * blockDim.x + threadIdx.x;
    if (i >= F2H_TOT) return;
    const float* src;
    __half* dst;
    int j;
    if (i < F2H_B0)      { src = s0; dst = d0; j = i; }
    else if (i < F2H_B1) { src = s1; dst = d1; j = i - F2H_B0; }
    else if (i < F2H_B2) { src = s2; dst = d2; j = i - F2H_B1; }
    else if (i < F2H_B3) { src = s3; dst = d3; j = i - F2H_B2; }
    else if (i < F2H_B4) { src = s4; dst = d4; j = i - F2H_B3; }
    else                 { src = s5; dst = d5; j = i - F2H_B4; }
    float4 v = ((const float4*)src)[j];
    ((__half2*)dst)[j * 2 + 0] = __floats2half2_rn(v.x, v.y);
    ((__half2*)dst)[j * 2 + 1] = __floats2half2_rn(v.z, v.w);
}

// ---------------- layernorm (cols = 768) ----------------
__global__ __launch_bounds__(256) void layernorm_kernel(
    const float* __restrict__ x, const float* __restrict__ add,
    const float* __restrict__ addb,
    const float* __restrict__ w, const float* __restrict__ b,
    float* __restrict__ out, __half* __restrict__ outh, int mode)
{
    int row = blockIdx.x;
    int tid = threadIdx.x;
    const size_t base = (size_t)row * DMODEL;
    float v[3];
    float s = 0.f;
    #pragma unroll
    for (int i = 0; i < 3; i++) {
        int c = tid + i * 256;
        float t = x[base + c];
        if (mode == 1) t += gelu_exact(add[base + c] + addb[c]);
        v[i] = t; s += t;
    }
    float mean = block_reduce_sum(s) * (1.0f / DMODEL);
    float sq = 0.f;
    #pragma unroll
    for (int i = 0; i < 3; i++) { float d = v[i] - mean; sq += d * d; }
    float var = block_reduce_sum(sq) * (1.0f / DMODEL);
    float rstd = rsqrtf(var + 1e-5f);
    #pragma unroll
    for (int i = 0; i < 3; i++) {
        int c = tid + i * 256;
        float r = (v[i] - mean) * rstd * w[c] + b[c];
        if (out)  out[base + c] = r;
        if (outh) outh[base + c] = __float2half_rn(r);
    }
}

// ---------------- WMMA HGEMM: CTA 128x128, 4 warps of 64x64, BK=32, 4-stage ----------------
// MODE 0: fp32 raw -> Cf ; MODE 1: fp16 raw -> Ch ; MODE 2: bias+gelu -> fp16 Ch
// NOTE: pipeline requires K/BK >= NSTAGE-1 (all our K: 24/48/96 k-tiles, fine)
#define BM 128
#define BN 128
#define BK 32
#define TPB 128
#define NSTAGE 4
#define ASTR 40
#define BSTR 136
#define AS_HALFS (BM * ASTR)
#define BS_HALFS (BK * BSTR)
#define STAGE_HALFS (AS_HALFS + BS_HALFS)
#define EPI_LDS 132
#define SMEM_PIPE ((size_t)(NSTAGE * STAGE_HALFS * 2))
#define SMEM_EPI  ((size_t)(BM * EPI_LDS * 4))
#define GEMM_SMEM_BYTES (SMEM_EPI > SMEM_PIPE ? SMEM_EPI : SMEM_PIPE)

__device__ __forceinline__ void hgemm_stage(
    const __half* __restrict__ A, const __half* __restrict__ W,
    int K, int N, int m0, int n0, int k0,
    __half* Asb, __half* Bsb, int tid)
{
    #pragma unroll
    for (int i = 0; i < 4; i++) {
        int c = tid + i * TPB;
        int row = c >> 2;
        int col8 = (c & 3) << 3;
        const __half* src = A + (size_t)(m0 + row) * K + k0 + col8;
        __pipeline_memcpy_async(Asb + row * ASTR + col8, src, 16);
    }
    #pragma unroll
    for (int i = 0; i < 4; i++) {
        int c = tid + i * TPB;
        int row = c >> 4;
        int col8 = (c & 15) << 3;
        __half* d = Bsb + row * BSTR + col8;
        if (n0 + col8 < N) {
            const __half* src = W + (size_t)(k0 + row) * N + n0 + col8;
            __pipeline_memcpy_async(d, src, 16);
        } else {
            *(float4*)d = make_float4(0.f, 0.f, 0.f, 0.f);
        }
    }
    __pipeline_commit();
}

template<int MODE>
__global__ __launch_bounds__(TPB) void hgemm_wmma(
    const __half* __restrict__ A, size_t aStride,
    const __half* __restrict__ W0, const __half* __restrict__ W1,
    const float* __restrict__ bias,
    float* __restrict__ Cf, __half* __restrict__ Ch, size_t outStride,
    int M, int N, int K, int ldc, int coff0, int coffStep)
{
    extern __shared__ __half smem[];

    const int tid  = threadIdx.x;
    const int wid  = tid >> 5;
    const int warp_m = wid & 1;
    const int warp_n = wid >> 1;
    const int m0 = blockIdx.y * BM;
    const int n0 = blockIdx.x * BN;
    const int z  = blockIdx.z;

    const __half* W = (z == 0) ? W0 : W1;
    A += (size_t)z * aStride;
    if (Cf) Cf += (size_t)z * outStride;
    if (Ch) Ch += (size_t)z * outStride;
    const int coff = coff0 + z * coffStep;

    wmma::fragment<wmma::accumulator, 16, 16, 16, float> cfr[4][4];
    #pragma unroll
    for (int i = 0; i < 4; i++) {
        #pragma unroll
        for (int j = 0; j < 4; j++) wmma::fill_fragment(cfr[i][j], 0.0f);
    }

    const int nK = K / BK;
    // prologue: fill NSTAGE-1 stages
    #pragma unroll
    for (int p = 0; p < NSTAGE - 1; p++) {
        if (p < nK) {
            __half* st = smem + p * STAGE_HALFS;
            hgemm_stage(A, W, K, N, m0, n0, p * BK, st, st + AS_HALFS, tid);
        }
    }

    for (int kt = 0; kt < nK; kt++) {
        __pipeline_wait_prior(NSTAGE - 2);
        __syncthreads();
        if (kt + NSTAGE - 1 < nK) {
            __half* st = smem + ((kt + NSTAGE - 1) % NSTAGE) * STAGE_HALFS;
            hgemm_stage(A, W, K, N, m0, n0, (kt + NSTAGE - 1) * BK, st, st + AS_HALFS, tid);
        }
        const __half* As = smem + (kt % NSTAGE) * STAGE_HALFS;
        const __half* Bs = As + AS_HALFS;

        #pragma unroll
        for (int kc = 0; kc < BK; kc += 16) {
            wmma::fragment<wmma::matrix_a, 16, 16, 16, __half, wmma::row_major> afr[4];
            wmma::fragment<wmma::matrix_b, 16, 16, 16, __half, wmma::row_major> bfr[4];
            #pragma unroll
            for (int i = 0; i < 4; i++) {
                wmma::load_matrix_sync(afr[i], As + (warp_m * 64 + i * 16) * ASTR + kc, ASTR);
            }
            #pragma unroll
            for (int j = 0; j < 4; j++) {
                wmma::load_matrix_sync(bfr[j], Bs + kc * BSTR + warp_n * 64 + j * 16, BSTR);
            }
            #pragma unroll
            for (int i = 0; i < 4; i++) {
                #pragma unroll
                for (int j = 0; j < 4; j++) {
                    wmma::mma_sync(cfr[i][j], afr[i], bfr[j], cfr[i][j]);
                }
            }
        }
    }

    if (MODE == 2) {
        __syncthreads();
        float* stg = (float*)smem;
        #pragma unroll
        for (int i = 0; i < 4; i++) {
            #pragma unroll
            for (int j = 0; j < 4; j++) {
                wmma::store_matrix_sync(stg + (warp_m * 64 + i * 16) * EPI_LDS + warp_n * 64 + j * 16,
                                        cfr[i][j], EPI_LDS, wmma::mem_row_major);
            }
        }
        __syncthreads();
        #pragma unroll
        for (int it = 0; it < 32; it++) {
            int q = tid + it * TPB;
            int r  = q >> 5;
            int c4 = (q & 31) << 2;
            int colb = n0 + c4;
            if (colb >= N) continue;
            float4 v = *(const float4*)(stg + r * EPI_LDS + c4);
            float r0 = gelu_exact(v.x + bias[colb + 0]);
            float r1 = gelu_exact(v.y + bias[colb + 1]);
            float r2 = gelu_exact(v.z + bias[colb + 2]);
            float r3 = gelu_exact(v.w + bias[colb + 3]);
            __half* dst = Ch + (size_t)(m0 + r) * ldc + coff + colb;
            ((__half2*)dst)[0] = __floats2half2_rn(r0, r1);
            ((__half2*)dst)[1] = __floats2half2_rn(r2, r3);
        }
    } else {
        #pragma unroll
        for (int i = 0; i < 4; i++) {
            #pragma unroll
            for (int j = 0; j < 4; j++) {
                int row = m0 + warp_m * 64 + i * 16;
                int col = n0 + warp_n * 64 + j * 16;
                if (MODE == 1) {
                    wmma::fragment<wmma::accumulator, 16, 16, 16, __half> hf;
                    #pragma unroll
                    for (int t = 0; t < hf.num_elements; t++) {
                        hf.x[t] = __float2half_rn(cfr[i][j].x[t]);
                    }
                    wmma::store_matrix_sync(Ch + (size_t)row * ldc + coff + col, hf, ldc, wmma::mem_row_major);
                } else {
                    wmma::store_matrix_sync(Cf + (size_t)row * ldc + coff + col, cfr[i][j], ldc, wmma::mem_row_major);
                }
            }
        }
    }
}

// ---------------- dt / dA (both directions) ----------------
__global__ void dtda_kernel(const __half* __restrict__ proj,
                            const float* __restrict__ dtb0, const float* __restrict__ dtb1,
                            const float* __restrict__ al0,  const float* __restrict__ al1,
                            float* __restrict__ dt, float* __restrict__ dA)
{
    int idx = blockIdx.x * blockDim.x + threadIdx.x;
    if (idx >= 2 * NTOK * NHEADS) return;
    int dir = idx / (NTOK * NHEADS);
    int rem = idx - dir * (NTOK * NHEADS);
    int h = rem % NHEADS;
    int j = rem / NHEADS;
    const float* dtb = dir ? dtb1 : dtb0;
    const float* al  = dir ? al1  : al0;
    float pv = __half2float(proj[(size_t)dir * NTOK * DPROJP + (size_t)j * DPROJP + (DINNER + CONVDIM) + h]);
    float raw = pv + dtb[h];
    float d = (raw > 20.f) ? raw : log1pf(expf(raw));
    float A = -expf(al[h]);
    dt[idx] = d;
    dA[idx] = expf(d * A);
}

// ---------------- depthwise conv + silu, 2 channels/thread -> fp16 ----------------
#define CONV2 (CONVDIM/2)   // 784
__global__ void conv_kernel(const __half* __restrict__ proj,
                            const float* __restrict__ cw0, const float* __restrict__ cw1,
                            const float* __restrict__ cb0, const float* __restrict__ cb1,
                            __half* __restrict__ out)
{
    int idx = blockIdx.x * blockDim.x + threadIdx.x;
    if (idx >= 2 * NTOK * CONV2) return;
    int dir = idx / (NTOK * CONV2);
    int rem = idx - dir * (NTOK * CONV2);
    int c2 = rem % CONV2;
    int row = rem / CONV2;
    int t = row % SEQ;
    int brow = row - t;
    int c = c2 * 2;
    const float* cw = dir ? cw1 : cw0;
    const float* cb = dir ? cb1 : cb0;
    const __half* pb = proj + (size_t)dir * NTOK * DPROJP;
    float acc0 = cb[c], acc1 = cb[c + 1];
    #pragma unroll
    for (int k = 0; k < DCONV; k++) {
        int tt = dir ? (t + (DCONV - 1) - k) : (t + k - (DCONV - 1));
        if (tt >= 0 && tt < SEQ) {
            __half2 pv = *(const __half2*)(pb + (size_t)(brow + tt) * DPROJP + DINNER + c);
            float2 p = __half22float2(pv);
            acc0 += cw[c * DCONV + k] * p.x;
            acc1 += cw[(c + 1) * DCONV + k] * p.y;
        }
    }
    __half2* ob = (__half2*)(out + (size_t)dir * NTOK * CONVDIM + (size_t)row * CONVDIM);
    ob[c2] = __floats2half2_rn(silu(acc0), silu(acc1));
}

// ---------------- selective scan: one CTA per (dir, batch, head) ----------------
#define SCHUNK 64
__global__ __launch_bounds__(512) void scan_kernel(
    const __half* __restrict__ conv, const float* __restrict__ dt,
    const float* __restrict__ dA,
    const float* __restrict__ Dp0, const float* __restrict__ Dp1,
    __half* __restrict__ y)
{
    int dir = blockIdx.x / (BATCH * NHEADS);
    int rem = blockIdx.x - dir * (BATCH * NHEADS);
    int b = rem / NHEADS;
    int h = rem % NHEADS;
    int tid = threadIdx.x;
    int n  = tid & 15;
    int pp = tid >> 4;
    int reverse = dir;

    const __half* convb = conv + (size_t)dir * NTOK * CONVDIM;
    const float* dtb   = dt   + (size_t)dir * NTOK * NHEADS;
    const float* dAb   = dA   + (size_t)dir * NTOK * NHEADS;
    __half* yb         = y    + (size_t)dir * NTOK * DINNER;
    const float Dv = dir ? Dp1[h] : Dp0[h];

    __shared__ float sx[SCHUNK][HEADDIM];
    __shared__ float sB[SCHUNK][DSTATE];
    __shared__ float sC[SCHUNK][DSTATE];
    __shared__ float sdt[SCHUNK];
    __shared__ float sdA[SCHUNK];

    float h0 = 0.f, h1 = 0.f;

    for (int c0 = 0; c0 < SEQ; c0 += SCHUNK) {
        #pragma unroll
        for (int i = 0; i < 8; i++) {
            int idx = i * 512 + tid;
            int s = idx >> 6, p = idx & 63;
            int t = reverse ? (SEQ - 1 - (c0 + s)) : (c0 + s);
            sx[s][p] = __half2float(convb[((size_t)(b * SEQ + t)) * CONVDIM + h * HEADDIM + p]);
        }
        #pragma unroll
        for (int i = 0; i < 2; i++) {
            int idx = i * 512 + tid;
            int s = idx >> 4, nn = idx & 15;
            int t = reverse ? (SEQ - 1 - (c0 + s)) : (c0 + s);
            size_t base = ((size_t)(b * SEQ + t)) * CONVDIM;
            sB[s][nn] = __half2float(convb[base + DINNER + nn]);
            sC[s][nn] = __half2float(convb[base + DINNER + DSTATE + nn]);
        }
        if (tid < SCHUNK) {
            int t = reverse ? (SEQ - 1 - (c0 + tid)) : (c0 + tid);
            sdt[tid] = dtb[(size_t)(b * SEQ + t) * NHEADS + h];
            sdA[tid] = dAb[(size_t)(b * SEQ + t) * NHEADS + h];
        }
        __syncthreads();

        #pragma unroll 4
        for (int s = 0; s < SCHUNK; s++) {
            float dAv = sdA[s], dtv = sdt[s];
            float Bn = sB[s][n], Cn = sC[s][n];
            float x0 = sx[s][pp], x1 = sx[s][pp + 32];
            h0 = h0 * dAv + (dtv * x0) * Bn;
            h1 = h1 * dAv + (dtv * x1) * Bn;
            float y0 = h0 * Cn, y1 = h1 * Cn;
            #pragma unroll
            for (int m = 8; m >= 1; m >>= 1) {
                y0 += __shfl_xor_sync(0xffffffffu, y0, m);
                y1 += __shfl_xor_sync(0xffffffffu, y1, m);
            }
            if (n == 0) {
                int t = reverse ? (SEQ - 1 - (c0 + s)) : (c0 + s);
                size_t o = ((size_t)(b * SEQ + t)) * DINNER + h * HEADDIM;
                yb[o + pp]      = __float2half_rn(y0 + Dv * x0);
                yb[o + pp + 32] = __float2half_rn(y1 + Dv * x1);
            }
        }
        __syncthreads();
    }
}

// ---------------- gate (y * silu(z)) + grouped RMSNorm -> fp16 (both dirs) ----------------
__global__ __launch_bounds__(256) void gate_rmsnorm_kernel(
    const __half* __restrict__ proj, const __half* __restrict__ y_in,
    const float* __restrict__ nw0, const float* __restrict__ nw1,
    __half* __restrict__ y_out)
{
    int dir = blockIdx.x >> 13;
    int row = blockIdx.x & (NTOK - 1);
    int tid = threadIdx.x;
    const __half* pb = proj + (size_t)dir * NTOK * DPROJP + (size_t)row * DPROJP;
    const __half* yb = y_in + (size_t)dir * NTOK * DINNER + (size_t)row * DINNER;
    __half* ob       = y_out + (size_t)dir * NTOK * DINNER + (size_t)row * DINNER;
    const float* nw  = dir ? nw1 : nw0;

    float v[6];
    float ss = 0.f;
    #pragma unroll
    for (int i = 0; i < 6; i++) {
        int c = tid + i * 256;
        float z  = __half2float(pb[c]);
        float yv = __half2float(yb[c]);
        float t = yv * silu(z);
        v[i] = t; ss += t * t;
    }
    float tot = block_reduce_sum(ss);
    float rs = rsqrtf(tot * (1.0f / DINNER) + 1e-5f);
    #pragma unroll
    for (int i = 0; i < 6; i++) {
        int c = tid + i * 256;
        ob[c] = __float2half_rn(v[i] * rs * nw[c]);
    }
}

// ---------------- host-side input binding by element count ----------------
static const float* pick(void* const* d_in, const int* sz, int n_in, int count, int occ) {
    int seen = 0;
    for (int i = 0; i < n_in; i++) {
        if (sz[i] == count) {
            if (seen == occ) return (const float*)d_in[i];
            seen++;
        }
    }
    return nullptr;
}

extern "C" void kernel_launch(void* const* d_in, const int* in_sizes, int n_in,
                              void* d_out, int out_size)
{
    const float* x      = pick(d_in, in_sizes, n_in, NTOK * DMODEL, 0);
    const float* ln1_w  = pick(d_in, in_sizes, n_in, 768, 0);
    const float* ln1_b  = pick(d_in, in_sizes, n_in, 768, 1);
    const float* ln2_w  = pick(d_in, in_sizes, n_in, 768, 2);
    const float* ln2_b  = pick(d_in, in_sizes, n_in, 768, 3);
    const float* ffn_b2 = pick(d_in, in_sizes, n_in, 768, 4);
    const float* ffn_w1 = pick(d_in, in_sizes, n_in, DINNER * DFFN, 0);
    const float* ffn_b1 = pick(d_in, in_sizes, n_in, DFFN, 0);
    const float* ffn_w2 = pick(d_in, in_sizes, n_in, DFFN * DMODEL, 0);

    const float* in_w0    = pick(d_in, in_sizes, n_in, DMODEL * DPROJ, 0);
    const float* in_w1    = pick(d_in, in_sizes, n_in, DMODEL * DPROJ, 1);
    const float* conv_w0  = pick(d_in, in_sizes, n_in, CONVDIM * DCONV, 0);
    const float* conv_w1  = pick(d_in, in_sizes, n_in, CONVDIM * DCONV, 1);
    const float* conv_b0  = pick(d_in, in_sizes, n_in, CONVDIM, 0);
    const float* conv_b1  = pick(d_in, in_sizes, n_in, CONVDIM, 1);
    const float* dt_bias0 = pick(d_in, in_sizes, n_in, NHEADS, 0);
    const float* dt_bias1 = pick(d_in, in_sizes, n_in, NHEADS, 3);
    const float* A_log0   = pick(d_in, in_sizes, n_in, NHEADS, 1);
    const float* A_log1   = pick(d_in, in_sizes, n_in, NHEADS, 4);
    const float* Dp0      = pick(d_in, in_sizes, n_in, NHEADS, 2);
    const float* Dp1      = pick(d_in, in_sizes, n_in, NHEADS, 5);
    const float* norm_w0  = pick(d_in, in_sizes, n_in, DINNER, 0);
    const float* norm_w1  = pick(d_in, in_sizes, n_in, DINNER, 1);
    const float* out_w0   = pick(d_in, in_sizes, n_in, DINNER * DMODEL, 0);
    const float* out_w1   = pick(d_in, in_sizes, n_in, DINNER * DMODEL, 1);

    __half* p_proj = 0; cudaGetSymbolAddress((void**)&p_proj, h_proj);
    __half* p_conv = 0; cudaGetSymbolAddress((void**)&p_conv, h_conv);
    float* p_dt   = 0;  cudaGetSymbolAddress((void**)&p_dt,   g_dt);
    float* p_dA   = 0;  cudaGetSymbolAddress((void**)&p_dA,   g_dA);
    __half* p_y   = 0;  cudaGetSymbolAddress((void**)&p_y,    h_y);
    float* p_h2   = 0;  cudaGetSymbolAddress((void**)&p_h2,   g_h2);

    __half* ph_xn  = 0; cudaGetSymbolAddress((void**)&ph_xn,  h_xn);
    __half* ph_yg  = 0; cudaGetSymbolAddress((void**)&ph_yg,  h_yg);
    __half* ph_bi  = 0; cudaGetSymbolAddress((void**)&ph_bi,  h_bi);
    __half* ph_ffn = 0; cudaGetSymbolAddress((void**)&ph_ffn, h_ffn);

    __half* pw_in0  = 0; cudaGetSymbolAddress((void**)&pw_in0,  hw_in0);
    __half* pw_in1  = 0; cudaGetSymbolAddress((void**)&pw_in1,  hw_in1);
    __half* pw_out0 = 0; cudaGetSymbolAddress((void**)&pw_out0, hw_out0);
    __half* pw_out1 = 0; cudaGetSymbolAddress((void**)&pw_out1, hw_out1);
    __half* pw_f1   = 0; cudaGetSymbolAddress((void**)&pw_f1,   hw_f1);
    __half* pw_f2   = 0; cudaGetSymbolAddress((void**)&pw_f2,   hw_f2);

    cudaFuncSetAttribute(hgemm_wmma<0>, cudaFuncAttributeMaxDynamicSharedMemorySize, GEMM_SMEM_BYTES);
    cudaFuncSetAttribute(hgemm_wmma<1>, cudaFuncAttributeMaxDynamicSharedMemorySize, GEMM_SMEM_BYTES);
    cudaFuncSetAttribute(hgemm_wmma<2>, cudaFuncAttributeMaxDynamicSharedMemorySize, GEMM_SMEM_BYTES);

    float* out = (float*)d_out;
    const int T = 256;

    // 1) merged weight conversion fp32 -> fp16 (single launch)
    f2h_all_kernel<<<(F2H_TOT + T - 1) / T, T>>>(
        in_w0, in_w1, out_w0, out_w1, ffn_w1, ffn_w2,
        pw_in0, pw_in1, pw_out0, pw_out1, pw_f1, pw_f2);

    // 2) LN1 -> fp16
    layernorm_kernel<<<NTOK, 256>>>(x, nullptr, nullptr, ln1_w, ln1_b, nullptr, ph_xn, 0);

    // 3) in_proj both dirs (z-batched) -> fp16 proj
    {
        dim3 grid(DPROJP / BN, NTOK / BM, 2);
        hgemm_wmma<1><<<grid, TPB, GEMM_SMEM_BYTES>>>(
            ph_xn, 0, pw_in0, pw_in1, nullptr,
            nullptr, p_proj, (size_t)NTOK * DPROJP,
            NTOK, DPROJ, DMODEL, DPROJP, 0, 0);
    }
    // 4) dt/dA both dirs
    dtda_kernel<<<(2 * NTOK * NHEADS + T - 1) / T, T>>>(p_proj, dt_bias0, dt_bias1, A_log0, A_log1, p_dt, p_dA);
    // 5) conv both dirs -> fp16
    conv_kernel<<<(2 * NTOK * CONV2 + T - 1) / T, T>>>(p_proj, conv_w0, conv_w1, conv_b0, conv_b1, p_conv);
    // 6) scan both dirs (192 CTAs) -> fp16 y   [captured by ncu -s 5 -c 1]
    scan_kernel<<<2 * BATCH * NHEADS, 512>>>(p_conv, p_dt, p_dA, Dp0, Dp1, p_y);
    // 7) gate + rmsnorm both dirs -> fp16
    gate_rmsnorm_kernel<<<2 * NTOK, 256>>>(p_proj, p_y, norm_w0, norm_w1, ph_yg);
    // 8) out_proj both dirs (z-batched) -> fp16 concat buffer
    {
        dim3 grid(DMODEL / BN, NTOK / BM, 2);
        hgemm_wmma<1><<<grid, TPB, GEMM_SMEM_BYTES>>>(
            ph_yg, (size_t)NTOK * DINNER, pw_out0, pw_out1, nullptr,
            nullptr, ph_bi, 0,
            NTOK, DMODEL, DINNER, DINNER, 0, DMODEL);
    }
    // 9) FFN1 with fused bias+gelu -> fp16
    {
        dim3 grid(DFFN / BN, NTOK / BM, 1);
        hgemm_wmma<2><<<grid, TPB, GEMM_SMEM_BYTES>>>(
            ph_bi, 0, pw_f1, pw_f1, ffn_b1,
            nullptr, ph_ffn, 0,
            NTOK, DFFN, DINNER, DFFN, 0, 0);
    }
    // 10) FFN2 -> fp32 raw
    {
        dim3 grid(DMODEL / BN, NTOK / BM, 1);
        hgemm_wmma<0><<<grid, TPB, GEMM_SMEM_BYTES>>>(
            ph_ffn, 0, pw_f2, pw_f2, nullptr,
            p_h2, nullptr, 0,
            NTOK, DMODEL, DFFN, DMODEL, 0, 0);
    }
    // 11) out = LN2(x + gelu(h2 + b2))
    layernorm_kernel<<<NTOK, 256>>>(x, p_h2, ffn_b2, ln2_w, ln2_b, out, nullptr, 1);
}

// round 12
// speedup vs baseline: 1.0177x; 1.0177x over previous
#include <cuda_runtime.h>
#include <cuda_fp16.h>
#include <cuda_pipeline.h>
#include <mma.h>
#include <math.h>

using namespace nvcuda;

// ---------------- problem constants ----------------
#define BATCH   4
#define SEQ     2048
#define DMODEL  768
#define DSTATE  16
#define DCONV   4
#define HEADDIM 64
#define DINNER  1536
#define NHEADS  24
#define CONVDIM 1568
#define DPROJ   3128
#define DPROJP  3328
#define NTOK    (BATCH*SEQ)
#define DFFN    3072

// ---------------- scratch (device globals; no allocation allowed) ----------------
__device__ __half h_proj[(size_t)2*NTOK*DPROJP];
__device__ __half h_conv[(size_t)2*NTOK*CONVDIM];
__device__ float  g_dt  [(size_t)2*NTOK*NHEADS];
__device__ float  g_dA  [(size_t)2*NTOK*NHEADS];
__device__ __half h_y   [(size_t)2*NTOK*DINNER];
__device__ __half h_yg  [(size_t)2*NTOK*DINNER];
__device__ float  g_h2  [(size_t)NTOK*DMODEL];

__device__ __half h_xn [(size_t)NTOK*DMODEL];
__device__ __half h_bi [(size_t)NTOK*DINNER];
__device__ __half h_ffn[(size_t)NTOK*DFFN];

// fp16 weight buffers
__device__ __half hw_in0 [(size_t)DMODEL*DPROJ];
__device__ __half hw_in1 [(size_t)DMODEL*DPROJ];
__device__ __half hw_out0[(size_t)DINNER*DMODEL];
__device__ __half hw_out1[(size_t)DINNER*DMODEL];
__device__ __half hw_f1  [(size_t)DINNER*DFFN];
__device__ __half hw_f2  [(size_t)DFFN*DMODEL];

// ---------------- helpers ----------------
__device__ __forceinline__ float gelu_exact(float x) {
    return 0.5f * x * (1.0f + erff(x * 0.70710678118654752f));
}
__device__ __forceinline__ float silu(float x) {
    return x / (1.0f + expf(-x));
}

__device__ float block_reduce_sum(float v) {
    __shared__ float sh[32];
    __shared__ float tot;
    int lane = threadIdx.x & 31, wid = threadIdx.x >> 5;
    #pragma unroll
    for (int m = 16; m >= 1; m >>= 1) v += __shfl_xor_sync(0xffffffffu, v, m);
    if (lane == 0) sh[wid] = v;
    __syncthreads();
    int nw = blockDim.x >> 5;
    v = (threadIdx.x < nw) ? sh[threadIdx.x] : 0.f;
    if (wid == 0) {
        #pragma unroll
        for (int m = 16; m >= 1; m >>= 1) v += __shfl_xor_sync(0xffffffffu, v, m);
        if (lane == 0) tot = v;
    }
    __syncthreads();
    return tot;
}

// ---------------- merged fp32 -> fp16 conversion for all 6 weights ----------------
#define N4_IN  (DMODEL*DPROJ/4)
#define N4_OUT (DINNER*DMODEL/4)
#define N4_F1  (DINNER*DFFN/4)
#define N4_F2  (DFFN*DMODEL/4)
#define F2H_B0 (N4_IN)
#define F2H_B1 (2*N4_IN)
#define F2H_B2 (2*N4_IN + N4_OUT)
#define F2H_B3 (2*N4_IN + 2*N4_OUT)
#define F2H_B4 (2*N4_IN + 2*N4_OUT + N4_F1)
#define F2H_TOT (2*N4_IN + 2*N4_OUT + N4_F1 + N4_F2)

__global__ void f2h_all_kernel(
    const float* __restrict__ s0, const float* __restrict__ s1,
    const float* __restrict__ s2, const float* __restrict__ s3,
    const float* __restrict__ s4, const float* __restrict__ s5,
    __half* __restrict__ d0, __half* __restrict__ d1,
    __half* __restrict__ d2, __half* __restrict__ d3,
    __half* __restrict__ d4, __half* __restrict__ d5)
{
    int i = blockIdx.x * blockDim.x + threadIdx.x;
    if (i >= F2H_TOT) return;
    const float* src;
    __half* dst;
    int j;
    if (i < F2H_B0)      { src = s0; dst = d0; j = i; }
    else if (i < F2H_B1) { src = s1; dst = d1; j = i - F2H_B0; }
    else if (i < F2H_B2) { src = s2; dst = d2; j = i - F2H_B1; }
    else if (i < F2H_B3) { src = s3; dst = d3; j = i - F2H_B2; }
    else if (i < F2H_B4) { src = s4; dst = d4; j = i - F2H_B3; }
    else                 { src = s5; dst = d5; j = i - F2H_B4; }
    float4 v = ((const float4*)src)[j];
    ((__half2*)dst)[j * 2 + 0] = __floats2half2_rn(v.x, v.y);
    ((__half2*)dst)[j * 2 + 1] = __floats2half2_rn(v.z, v.w);
}

// ---------------- layernorm (cols = 768) ----------------
__global__ __launch_bounds__(256) void layernorm_kernel(
    const float* __restrict__ x, const float* __restrict__ add,
    const float* __restrict__ addb,
    const float* __restrict__ w, const float* __restrict__ b,
    float* __restrict__ out, __half* __restrict__ outh, int mode)
{
    int row = blockIdx.x;
    int tid = threadIdx.x;
    const size_t base = (size_t)row * DMODEL;
    float v[3];
    float s = 0.f;
    #pragma unroll
    for (int i = 0; i < 3; i++) {
        int c = tid + i * 256;
        float t = x[base + c];
        if (mode == 1) t += gelu_exact(add[base + c] + addb[c]);
        v[i] = t; s += t;
    }
    float mean = block_reduce_sum(s) * (1.0f / DMODEL);
    float sq = 0.f;
    #pragma unroll
    for (int i = 0; i < 3; i++) { float d = v[i] - mean; sq += d * d; }
    float var = block_reduce_sum(sq) * (1.0f / DMODEL);
    float rstd = rsqrtf(var + 1e-5f);
    #pragma unroll
    for (int i = 0; i < 3; i++) {
        int c = tid + i * 256;
        float r = (v[i] - mean) * rstd * w[c] + b[c];
        if (out)  out[base + c] = r;
        if (outh) outh[base + c] = __float2half_rn(r);
    }
}

// ---------------- WMMA HGEMM: CTA 128x128, 4 warps of 64x64, BK=32, 3-stage ----------------
// MODE 0: fp32 raw -> Cf ; MODE 1: fp16 raw -> Ch ; MODE 2: bias+gelu -> fp16 Ch
#define BM 128
#define BN 128
#define BK 32
#define TPB 128
#define NSTAGE 3
#define ASTR 40
#define BSTR 136
#define AS_HALFS (BM * ASTR)
#define BS_HALFS (BK * BSTR)
#define STAGE_HALFS (AS_HALFS + BS_HALFS)
#define EPI_LDS 132
#define SMEM_PIPE ((size_t)(NSTAGE * STAGE_HALFS * 2))
#define SMEM_EPI  ((size_t)(BM * EPI_LDS * 4))
#define GEMM_SMEM_BYTES (SMEM_EPI > SMEM_PIPE ? SMEM_EPI : SMEM_PIPE)

__device__ __forceinline__ void hgemm_stage(
    const __half* __restrict__ A, const __half* __restrict__ W,
    int K, int N, int m0, int n0, int k0,
    __half* Asb, __half* Bsb, int tid)
{
    #pragma unroll
    for (int i = 0; i < 4; i++) {
        int c = tid + i * TPB;
        int row = c >> 2;
        int col8 = (c & 3) << 3;
        const __half* src = A + (size_t)(m0 + row) * K + k0 + col8;
        __pipeline_memcpy_async(Asb + row * ASTR + col8, src, 16);
    }
    #pragma unroll
    for (int i = 0; i < 4; i++) {
        int c = tid + i * TPB;
        int row = c >> 4;
        int col8 = (c & 15) << 3;
        __half* d = Bsb + row * BSTR + col8;
        if (n0 + col8 < N) {
            const __half* src = W + (size_t)(k0 + row) * N + n0 + col8;
            __pipeline_memcpy_async(d, src, 16);
        } else {
            *(float4*)d = make_float4(0.f, 0.f, 0.f, 0.f);
        }
    }
    __pipeline_commit();
}

template<int MODE>
__global__ __launch_bounds__(TPB) void hgemm_wmma(
    const __half* __restrict__ A, size_t aStride,
    const __half* __restrict__ W0, const __half* __restrict__ W1,
    const float* __restrict__ bias,
    float* __restrict__ Cf, __half* __restrict__ Ch, size_t outStride,
    int M, int N, int K, int ldc, int coff0, int coffStep)
{
    extern __shared__ __half smem[];

    const int tid  = threadIdx.x;
    const int wid  = tid >> 5;
    const int warp_m = wid & 1;
    const int warp_n = wid >> 1;
    const int m0 = blockIdx.y * BM;
    const int n0 = blockIdx.x * BN;
    const int z  = blockIdx.z;

    const __half* W = (z == 0) ? W0 : W1;
    A += (size_t)z * aStride;
    if (Cf) Cf += (size_t)z * outStride;
    if (Ch) Ch += (size_t)z * outStride;
    const int coff = coff0 + z * coffStep;

    wmma::fragment<wmma::accumulator, 16, 16, 16, float> cfr[4][4];
    #pragma unroll
    for (int i = 0; i < 4; i++) {
        #pragma unroll
        for (int j = 0; j < 4; j++) wmma::fill_fragment(cfr[i][j], 0.0f);
    }

    const int nK = K / BK;
    hgemm_stage(A, W, K, N, m0, n0, 0, smem, smem + AS_HALFS, tid);
    if (nK > 1) {
        __half* st = smem + STAGE_HALFS;
        hgemm_stage(A, W, K, N, m0, n0, BK, st, st + AS_HALFS, tid);
    }

    for (int kt = 0; kt < nK; kt++) {
        __pipeline_wait_prior(NSTAGE - 2);
        __syncthreads();
        if (kt + 2 < nK) {
            __half* st = smem + ((kt + 2) % NSTAGE) * STAGE_HALFS;
            hgemm_stage(A, W, K, N, m0, n0, (kt + 2) * BK, st, st + AS_HALFS, tid);
        }
        const __half* As = smem + (kt % NSTAGE) * STAGE_HALFS;
        const __half* Bs = As + AS_HALFS;

        #pragma unroll
        for (int kc = 0; kc < BK; kc += 16) {
            wmma::fragment<wmma::matrix_a, 16, 16, 16, __half, wmma::row_major> afr[4];
            wmma::fragment<wmma::matrix_b, 16, 16, 16, __half, wmma::row_major> bfr[4];
            #pragma unroll
            for (int i = 0; i < 4; i++) {
                wmma::load_matrix_sync(afr[i], As + (warp_m * 64 + i * 16) * ASTR + kc, ASTR);
            }
            #pragma unroll
            for (int j = 0; j < 4; j++) {
                wmma::load_matrix_sync(bfr[j], Bs + kc * BSTR + warp_n * 64 + j * 16, BSTR);
            }
            #pragma unroll
            for (int i = 0; i < 4; i++) {
                #pragma unroll
                for (int j = 0; j < 4; j++) {
                    wmma::mma_sync(cfr[i][j], afr[i], bfr[j], cfr[i][j]);
                }
            }
        }
    }

    if (MODE == 2) {
        __syncthreads();
        float* stg = (float*)smem;
        #pragma unroll
        for (int i = 0; i < 4; i++) {
            #pragma unroll
            for (int j = 0; j < 4; j++) {
                wmma::store_matrix_sync(stg + (warp_m * 64 + i * 16) * EPI_LDS + warp_n * 64 + j * 16,
                                        cfr[i][j], EPI_LDS, wmma::mem_row_major);
            }
        }
        __syncthreads();
        #pragma unroll
        for (int it = 0; it < 32; it++) {
            int q = tid + it * TPB;
            int r  = q >> 5;
            int c4 = (q & 31) << 2;
            int colb = n0 + c4;
            if (colb >= N) continue;
            float4 v = *(const float4*)(stg + r * EPI_LDS + c4);
            float r0 = gelu_exact(v.x + bias[colb + 0]);
            float r1 = gelu_exact(v.y + bias[colb + 1]);
            float r2 = gelu_exact(v.z + bias[colb + 2]);
            float r3 = gelu_exact(v.w + bias[colb + 3]);
            __half* dst = Ch + (size_t)(m0 + r) * ldc + coff + colb;
            ((__half2*)dst)[0] = __floats2half2_rn(r0, r1);
            ((__half2*)dst)[1] = __floats2half2_rn(r2, r3);
        }
    } else {
        #pragma unroll
        for (int i = 0; i < 4; i++) {
            #pragma unroll
            for (int j = 0; j < 4; j++) {
                int row = m0 + warp_m * 64 + i * 16;
                int col = n0 + warp_n * 64 + j * 16;
                if (MODE == 1) {
                    wmma::fragment<wmma::accumulator, 16, 16, 16, __half> hf;
                    #pragma unroll
                    for (int t = 0; t < hf.num_elements; t++) {
                        hf.x[t] = __float2half_rn(cfr[i][j].x[t]);
                    }
                    wmma::store_matrix_sync(Ch + (size_t)row * ldc + coff + col, hf, ldc, wmma::mem_row_major);
                } else {
                    wmma::store_matrix_sync(Cf + (size_t)row * ldc + coff + col, cfr[i][j], ldc, wmma::mem_row_major);
                }
            }
        }
    }
}

// ---------------- dt / dA (both directions) ----------------
__global__ void dtda_kernel(const __half* __restrict__ proj,
                            const float* __restrict__ dtb0, const float* __restrict__ dtb1,
                            const float* __restrict__ al0,  const float* __restrict__ al1,
                            float* __restrict__ dt, float* __restrict__ dA)
{
    int idx = blockIdx.x * blockDim.x + threadIdx.x;
    if (idx >= 2 * NTOK * NHEADS) return;
    int dir = idx / (NTOK * NHEADS);
    int rem = idx - dir * (NTOK * NHEADS);
    int h = rem % NHEADS;
    int j = rem / NHEADS;
    const float* dtb = dir ? dtb1 : dtb0;
    const float* al  = dir ? al1  : al0;
    float pv = __half2float(proj[(size_t)dir * NTOK * DPROJP + (size_t)j * DPROJP + (DINNER + CONVDIM) + h]);
    float raw = pv + dtb[h];
    float d = (raw > 20.f) ? raw : log1pf(expf(raw));
    float A = -expf(al[h]);
    dt[idx] = d;
    dA[idx] = expf(d * A);
}

// ---------------- depthwise conv + silu, 2 channels/thread -> fp16 ----------------
#define CONV2 (CONVDIM/2)
__global__ void conv_kernel(const __half* __restrict__ proj,
                            const float* __restrict__ cw0, const float* __restrict__ cw1,
                            const float* __restrict__ cb0, const float* __restrict__ cb1,
                            __half* __restrict__ out)
{
    int idx = blockIdx.x * blockDim.x + threadIdx.x;
    if (idx >= 2 * NTOK * CONV2) return;
    int dir = idx / (NTOK * CONV2);
    int rem = idx - dir * (NTOK * CONV2);
    int c2 = rem % CONV2;
    int row = rem / CONV2;
    int t = row % SEQ;
    int brow = row - t;
    int c = c2 * 2;
    const float* cw = dir ? cw1 : cw0;
    const float* cb = dir ? cb1 : cb0;
    const __half* pb = proj + (size_t)dir * NTOK * DPROJP;
    float acc0 = cb[c], acc1 = cb[c + 1];
    #pragma unroll
    for (int k = 0; k < DCONV; k++) {
        int tt = dir ? (t + (DCONV - 1) - k) : (t + k - (DCONV - 1));
        if (tt >= 0 && tt < SEQ) {
            __half2 pv = *(const __half2*)(pb + (size_t)(brow + tt) * DPROJP + DINNER + c);
            float2 p = __half22float2(pv);
            acc0 += cw[c * DCONV + k] * p.x;
            acc1 += cw[(c + 1) * DCONV + k] * p.y;
        }
    }
    __half2* ob = (__half2*)(out + (size_t)dir * NTOK * CONVDIM + (size_t)row * CONVDIM);
    ob[c2] = __floats2half2_rn(silu(acc0), silu(acc1));
}

// ---------------- selective scan: one CTA per (dir, batch, head) ----------------
#define SCHUNK 64
__global__ __launch_bounds__(512) void scan_kernel(
    const __half* __restrict__ conv, const float* __restrict__ dt,
    const float* __restrict__ dA,
    const float* __restrict__ Dp0, const float* __restrict__ Dp1,
    __half* __restrict__ y)
{
    int dir = blockIdx.x / (BATCH * NHEADS);
    int rem = blockIdx.x - dir * (BATCH * NHEADS);
    int b = rem / NHEADS;
    int h = rem % NHEADS;
    int tid = threadIdx.x;
    int n  = tid & 15;
    int pp = tid >> 4;
    int reverse = dir;

    const __half* convb = conv + (size_t)dir * NTOK * CONVDIM;
    const float* dtb   = dt   + (size_t)dir * NTOK * NHEADS;
    const float* dAb   = dA   + (size_t)dir * NTOK * NHEADS;
    __half* yb         = y    + (size_t)dir * NTOK * DINNER;
    const float Dv = dir ? Dp1[h] : Dp0[h];

    __shared__ float sx[SCHUNK][HEADDIM];
    __shared__ float sB[SCHUNK][DSTATE];
    __shared__ float sC[SCHUNK][DSTATE];
    __shared__ float sdt[SCHUNK];
    __shared__ float sdA[SCHUNK];

    float h0 = 0.f, h1 = 0.f;

    for (int c0 = 0; c0 < SEQ; c0 += SCHUNK) {
        #pragma unroll
        for (int i = 0; i < 8; i++) {
            int idx = i * 512 + tid;
            int s = idx >> 6, p = idx & 63;
            int t = reverse ? (SEQ - 1 - (c0 + s)) : (c0 + s);
            sx[s][p] = __half2float(convb[((size_t)(b * SEQ + t)) * CONVDIM + h * HEADDIM + p]);
        }
        #pragma unroll
        for (int i = 0; i < 2; i++) {
            int idx = i * 512 + tid;
            int s = idx >> 4, nn = idx & 15;
            int t = reverse ? (SEQ - 1 - (c0 + s)) : (c0 + s);
            size_t base = ((size_t)(b * SEQ + t)) * CONVDIM;
            sB[s][nn] = __half2float(convb[base + DINNER + nn]);
            sC[s][nn] = __half2float(convb[base + DINNER + DSTATE + nn]);
        }
        if (tid < SCHUNK) {
            int t = reverse ? (SEQ - 1 - (c0 + tid)) : (c0 + tid);
            sdt[tid] = dtb[(size_t)(b * SEQ + t) * NHEADS + h];
            sdA[tid] = dAb[(size_t)(b * SEQ + t) * NHEADS + h];
        }
        __syncthreads();

        #pragma unroll 4
        for (int s = 0; s < SCHUNK; s++) {
            float dAv = sdA[s], dtv = sdt[s];
            float Bn = sB[s][n], Cn = sC[s][n];
            float x0 = sx[s][pp], x1 = sx[s][pp + 32];
            h0 = h0 * dAv + (dtv * x0) * Bn;
            h1 = h1 * dAv + (dtv * x1) * Bn;
            float y0 = h0 * Cn, y1 = h1 * Cn;
            #pragma unroll
            for (int m = 8; m >= 1; m >>= 1) {
                y0 += __shfl_xor_sync(0xffffffffu, y0, m);
                y1 += __shfl_xor_sync(0xffffffffu, y1, m);
            }
            if (n == 0) {
                int t = reverse ? (SEQ - 1 - (c0 + s)) : (c0 + s);
                size_t o = ((size_t)(b * SEQ + t)) * DINNER + h * HEADDIM;
                yb[o + pp]      = __float2half_rn(y0 + Dv * x0);
                yb[o + pp + 32] = __float2half_rn(y1 + Dv * x1);
            }
        }
        __syncthreads();
    }
}

// ---------------- gate (y * silu(z)) + grouped RMSNorm -> fp16 (both dirs) ----------------
__global__ __launch_bounds__(256) void gate_rmsnorm_kernel(
    const __half* __restrict__ proj, const __half* __restrict__ y_in,
    const float* __restrict__ nw0, const float* __restrict__ nw1,
    __half* __restrict__ y_out)
{
    int dir = blockIdx.x >> 13;
    int row = blockIdx.x & (NTOK - 1);
    int tid = threadIdx.x;
    const __half* pb = proj + (size_t)dir * NTOK * DPROJP + (size_t)row * DPROJP;
    const __half* yb = y_in + (size_t)dir * NTOK * DINNER + (size_t)row * DINNER;
    __half* ob       = y_out + (size_t)dir * NTOK * DINNER + (size_t)row * DINNER;
    const float* nw  = dir ? nw1 : nw0;

    float v[6];
    float ss = 0.f;
    #pragma unroll
    for (int i = 0; i < 6; i++) {
        int c = tid + i * 256;
        float z  = __half2float(pb[c]);
        float yv = __half2float(yb[c]);
        float t = yv * silu(z);
        v[i] = t; ss += t * t;
    }
    float tot = block_reduce_sum(ss);
    float rs = rsqrtf(tot * (1.0f / DINNER) + 1e-5f);
    #pragma unroll
    for (int i = 0; i < 6; i++) {
        int c = tid + i * 256;
        ob[c] = __float2half_rn(v[i] * rs * nw[c]);
    }
}

// ---------------- host-side input binding by element count ----------------
static const float* pick(void* const* d_in, const int* sz, int n_in, int count, int occ) {
    int seen = 0;
    for (int i = 0; i < n_in; i++) {
        if (sz[i] == count) {
            if (seen == occ) return (const float*)d_in[i];
            seen++;
        }
    }
    return nullptr;
}

extern "C" void kernel_launch(void* const* d_in, const int* in_sizes, int n_in,
                              void* d_out, int out_size)
{
    const float* x      = pick(d_in, in_sizes, n_in, NTOK * DMODEL, 0);
    const float* ln1_w  = pick(d_in, in_sizes, n_in, 768, 0);
    const float* ln1_b  = pick(d_in, in_sizes, n_in, 768, 1);
    const float* ln2_w  = pick(d_in, in_sizes, n_in, 768, 2);
    const float* ln2_b  = pick(d_in, in_sizes, n_in, 768, 3);
    const float* ffn_b2 = pick(d_in, in_sizes, n_in, 768, 4);
    const float* ffn_w1 = pick(d_in, in_sizes, n_in, DINNER * DFFN, 0);
    const float* ffn_b1 = pick(d_in, in_sizes, n_in, DFFN, 0);
    const float* ffn_w2 = pick(d_in, in_sizes, n_in, DFFN * DMODEL, 0);

    const float* in_w0    = pick(d_in, in_sizes, n_in, DMODEL * DPROJ, 0);
    const float* in_w1    = pick(d_in, in_sizes, n_in, DMODEL * DPROJ, 1);
    const float* conv_w0  = pick(d_in, in_sizes, n_in, CONVDIM * DCONV, 0);
    const float* conv_w1  = pick(d_in, in_sizes, n_in, CONVDIM * DCONV, 1);
    const float* conv_b0  = pick(d_in, in_sizes, n_in, CONVDIM, 0);
    const float* conv_b1  = pick(d_in, in_sizes, n_in, CONVDIM, 1);
    const float* dt_bias0 = pick(d_in, in_sizes, n_in, NHEADS, 0);
    const float* dt_bias1 = pick(d_in, in_sizes, n_in, NHEADS, 3);
    const float* A_log0   = pick(d_in, in_sizes, n_in, NHEADS, 1);
    const float* A_log1   = pick(d_in, in_sizes, n_in, NHEADS, 4);
    const float* Dp0      = pick(d_in, in_sizes, n_in, NHEADS, 2);
    const float* Dp1      = pick(d_in, in_sizes, n_in, NHEADS, 5);
    const float* norm_w0  = pick(d_in, in_sizes, n_in, DINNER, 0);
    const float* norm_w1  = pick(d_in, in_sizes, n_in, DINNER, 1);
    const float* out_w0   = pick(d_in, in_sizes, n_in, DINNER * DMODEL, 0);
    const float* out_w1   = pick(d_in, in_sizes, n_in, DINNER * DMODEL, 1);

    __half* p_proj = 0; cudaGetSymbolAddress((void**)&p_proj, h_proj);
    __half* p_conv = 0; cudaGetSymbolAddress((void**)&p_conv, h_conv);
    float* p_dt   = 0;  cudaGetSymbolAddress((void**)&p_dt,   g_dt);
    float* p_dA   = 0;  cudaGetSymbolAddress((void**)&p_dA,   g_dA);
    __half* p_y   = 0;  cudaGetSymbolAddress((void**)&p_y,    h_y);
    float* p_h2   = 0;  cudaGetSymbolAddress((void**)&p_h2,   g_h2);

    __half* ph_xn  = 0; cudaGetSymbolAddress((void**)&ph_xn,  h_xn);
    __half* ph_yg  = 0; cudaGetSymbolAddress((void**)&ph_yg,  h_yg);
    __half* ph_bi  = 0; cudaGetSymbolAddress((void**)&ph_bi,  h_bi);
    __half* ph_ffn = 0; cudaGetSymbolAddress((void**)&ph_ffn, h_ffn);

    __half* pw_in0  = 0; cudaGetSymbolAddress((void**)&pw_in0,  hw_in0);
    __half* pw_in1  = 0; cudaGetSymbolAddress((void**)&pw_in1,  hw_in1);
    __half* pw_out0 = 0; cudaGetSymbolAddress((void**)&pw_out0, hw_out0);
    __half* pw_out1 = 0; cudaGetSymbolAddress((void**)&pw_out1, hw_out1);
    __half* pw_f1   = 0; cudaGetSymbolAddress((void**)&pw_f1,   hw_f1);
    __half* pw_f2   = 0; cudaGetSymbolAddress((void**)&pw_f2,   hw_f2);

    cudaFuncSetAttribute(hgemm_wmma<0>, cudaFuncAttributeMaxDynamicSharedMemorySize, GEMM_SMEM_BYTES);
    cudaFuncSetAttribute(hgemm_wmma<1>, cudaFuncAttributeMaxDynamicSharedMemorySize, GEMM_SMEM_BYTES);
    cudaFuncSetAttribute(hgemm_wmma<2>, cudaFuncAttributeMaxDynamicSharedMemorySize, GEMM_SMEM_BYTES);

    float* out = (float*)d_out;
    const int T = 256;

    // 1) merged weight conversion fp32 -> fp16 (single launch)
    f2h_all_kernel<<<(F2H_TOT + T - 1) / T, T>>>(
        in_w0, in_w1, out_w0, out_w1, ffn_w1, ffn_w2,
        pw_in0, pw_in1, pw_out0, pw_out1, pw_f1, pw_f2);

    // 2) LN1 -> fp16
    layernorm_kernel<<<NTOK, 256>>>(x, nullptr, nullptr, ln1_w, ln1_b, nullptr, ph_xn, 0);

    // 3) in_proj both dirs (z-batched) -> fp16 proj
    //    grid.x trimmed to ceil(DPROJ/BN)=25 (26th block is pure padding)
    {
        dim3 grid((DPROJ + BN - 1) / BN, NTOK / BM, 2);
        hgemm_wmma<1><<<grid, TPB, GEMM_SMEM_BYTES>>>(
            ph_xn, 0, pw_in0, pw_in1, nullptr,
            nullptr, p_proj, (size_t)NTOK * DPROJP,
            NTOK, DPROJ, DMODEL, DPROJP, 0, 0);
    }
    // 4) dt/dA both dirs
    dtda_kernel<<<(2 * NTOK * NHEADS + T - 1) / T, T>>>(p_proj, dt_bias0, dt_bias1, A_log0, A_log1, p_dt, p_dA);
    // 5) conv both dirs -> fp16
    conv_kernel<<<(2 * NTOK * CONV2 + T - 1) / T, T>>>(p_proj, conv_w0, conv_w1, conv_b0, conv_b1, p_conv);
    // 6) scan both dirs (192 CTAs) -> fp16 y
    scan_kernel<<<2 * BATCH * NHEADS, 512>>>(p_conv, p_dt, p_dA, Dp0, Dp1, p_y);
    // 7) gate + rmsnorm both dirs -> fp16
    gate_rmsnorm_kernel<<<2 * NTOK, 256>>>(p_proj, p_y, norm_w0, norm_w1, ph_yg);
    // 8) out_proj both dirs (z-batched) -> fp16 concat buffer
    {
        dim3 grid(DMODEL / BN, NTOK / BM, 2);
        hgemm_wmma<1><<<grid, TPB, GEMM_SMEM_BYTES>>>(
            ph_yg, (size_t)NTOK * DINNER, pw_out0, pw_out1, nullptr,
            nullptr, ph_bi, 0,
            NTOK, DMODEL, DINNER, DINNER, 0, DMODEL);
    }
    // 9) FFN1 with fused bias+gelu -> fp16
    {
        dim3 grid(DFFN / BN, NTOK / BM, 1);
        hgemm_wmma<2><<<grid, TPB, GEMM_SMEM_BYTES>>>(
            ph_bi, 0, pw_f1, pw_f1, ffn_b1,
            nullptr, ph_ffn, 0,
            NTOK, DFFN, DINNER, DFFN, 0, 0);
    }
    // 10) FFN2 -> fp32 raw
    {
        dim3 grid(DMODEL / BN, NTOK / BM, 1);
        hgemm_wmma<0><<<grid, TPB, GEMM_SMEM_BYTES>>>(
            ph_ffn, 0, pw_f2, pw_f2, nullptr,
            p_h2, nullptr, 0,
            NTOK, DMODEL, DFFN, DMODEL, 0, 0);
    }
    // 11) out = LN2(x + gelu(h2 + b2))
    layernorm_kernel<<<NTOK, 256>>>(x, p_h2, ffn_b2, ln2_w, ln2_b, out, nullptr, 1);
}

// round 13
// speedup vs baseline: 1.2618x; 1.2398x over previous
#include <cuda_runtime.h>
#include <cuda_fp16.h>
#include <cuda_pipeline.h>
#include <mma.h>
#include <math.h>

using namespace nvcuda;

// ---------------- problem constants ----------------
#define BATCH   4
#define SEQ     2048
#define DMODEL  768
#define DSTATE  16
#define DCONV   4
#define HEADDIM 64
#define DINNER  1536
#define NHEADS  24
#define CONVDIM 1568
#define DPROJ   3128
#define DPROJP  3328
#define NTOK    (BATCH*SEQ)
#define DFFN    3072

// ---------------- scratch (device globals; no allocation allowed) ----------------
__device__ __half h_proj[(size_t)2*NTOK*DPROJP];
__device__ __half h_conv[(size_t)2*NTOK*CONVDIM];
__device__ float  g_dt  [(size_t)2*NTOK*NHEADS];
__device__ float  g_dA  [(size_t)2*NTOK*NHEADS];
__device__ __half h_y   [(size_t)2*NTOK*DINNER];
__device__ __half h_yg  [(size_t)2*NTOK*DINNER];
__device__ float  g_h2  [(size_t)NTOK*DMODEL];

__device__ __half h_xn [(size_t)NTOK*DMODEL];
__device__ __half h_bi [(size_t)NTOK*DINNER];
__device__ __half h_ffn[(size_t)NTOK*DFFN];

// fp16 weight buffers
__device__ __half hw_in0 [(size_t)DMODEL*DPROJ];
__device__ __half hw_in1 [(size_t)DMODEL*DPROJ];
__device__ __half hw_out0[(size_t)DINNER*DMODEL];
__device__ __half hw_out1[(size_t)DINNER*DMODEL];
__device__ __half hw_f1  [(size_t)DINNER*DFFN];
__device__ __half hw_f2  [(size_t)DFFN*DMODEL];

// ---------------- helpers ----------------
__device__ __forceinline__ float gelu_exact(float x) {
    return 0.5f * x * (1.0f + erff(x * 0.70710678118654752f));
}
__device__ __forceinline__ float silu(float x) {
    return x / (1.0f + expf(-x));
}

__device__ float block_reduce_sum(float v) {
    __shared__ float sh[32];
    __shared__ float tot;
    int lane = threadIdx.x & 31, wid = threadIdx.x >> 5;
    #pragma unroll
    for (int m = 16; m >= 1; m >>= 1) v += __shfl_xor_sync(0xffffffffu, v, m);
    if (lane == 0) sh[wid] = v;
    __syncthreads();
    int nw = blockDim.x >> 5;
    v = (threadIdx.x < nw) ? sh[threadIdx.x] : 0.f;
    if (wid == 0) {
        #pragma unroll
        for (int m = 16; m >= 1; m >>= 1) v += __shfl_xor_sync(0xffffffffu, v, m);
        if (lane == 0) tot = v;
    }
    __syncthreads();
    return tot;
}

// ---------------- merged fp32 -> fp16 conversion for all 6 weights ----------------
#define N4_IN  (DMODEL*DPROJ/4)
#define N4_OUT (DINNER*DMODEL/4)
#define N4_F1  (DINNER*DFFN/4)
#define N4_F2  (DFFN*DMODEL/4)
#define F2H_B0 (N4_IN)
#define F2H_B1 (2*N4_IN)
#define F2H_B2 (2*N4_IN + N4_OUT)
#define F2H_B3 (2*N4_IN + 2*N4_OUT)
#define F2H_B4 (2*N4_IN + 2*N4_OUT + N4_F1)
#define F2H_TOT (2*N4_IN + 2*N4_OUT + N4_F1 + N4_F2)

__global__ void f2h_all_kernel(
    const float* __restrict__ s0, const float* __restrict__ s1,
    const float* __restrict__ s2, const float* __restrict__ s3,
    const float* __restrict__ s4, const float* __restrict__ s5,
    __half* __restrict__ d0, __half* __restrict__ d1,
    __half* __restrict__ d2, __half* __restrict__ d3,
    __half* __restrict__ d4, __half* __restrict__ d5)
{
    int i = blockIdx.x * blockDim.x + threadIdx.x;
    if (i >= F2H_TOT) return;
    const float* src;
    __half* dst;
    int j;
    if (i < F2H_B0)      { src = s0; dst = d0; j = i; }
    else if (i < F2H_B1) { src = s1; dst = d1; j = i - F2H_B0; }
    else if (i < F2H_B2) { src = s2; dst = d2; j = i - F2H_B1; }
    else if (i < F2H_B3) { src = s3; dst = d3; j = i - F2H_B2; }
    else if (i < F2H_B4) { src = s4; dst = d4; j = i - F2H_B3; }
    else                 { src = s5; dst = d5; j = i - F2H_B4; }
    float4 v = ((const float4*)src)[j];
    ((__half2*)dst)[j * 2 + 0] = __floats2half2_rn(v.x, v.y);
    ((__half2*)dst)[j * 2 + 1] = __floats2half2_rn(v.z, v.w);
}

// ---------------- layernorm (cols = 768) ----------------
__global__ __launch_bounds__(256) void layernorm_kernel(
    const float* __restrict__ x, const float* __restrict__ add,
    const float* __restrict__ addb,
    const float* __restrict__ w, const float* __restrict__ b,
    float* __restrict__ out, __half* __restrict__ outh, int mode)
{
    int row = blockIdx.x;
    int tid = threadIdx.x;
    const size_t base = (size_t)row * DMODEL;
    float v[3];
    float s = 0.f;
    #pragma unroll
    for (int i = 0; i < 3; i++) {
        int c = tid + i * 256;
        float t = x[base + c];
        if (mode == 1) t += gelu_exact(add[base + c] + addb[c]);
        v[i] = t; s += t;
    }
    float mean = block_reduce_sum(s) * (1.0f / DMODEL);
    float sq = 0.f;
    #pragma unroll
    for (int i = 0; i < 3; i++) { float d = v[i] - mean; sq += d * d; }
    float var = block_reduce_sum(sq) * (1.0f / DMODEL);
    float rstd = rsqrtf(var + 1e-5f);
    #pragma unroll
    for (int i = 0; i < 3; i++) {
        int c = tid + i * 256;
        float r = (v[i] - mean) * rstd * w[c] + b[c];
        if (out)  out[base + c] = r;
        if (outh) outh[base + c] = __float2half_rn(r);
    }
}

// ---------------- WMMA HGEMM: CTA 128x128, 4 warps of 64x64, BK=32, 3-stage ----------------
// MODE 0: fp32 raw -> Cf ; MODE 1: fp16 raw -> Ch ; MODE 2: bias+gelu -> fp16 Ch
#define BM 128
#define BN 128
#define BK 32
#define TPB 128
#define NSTAGE 3
#define ASTR 40
#define BSTR 136
#define AS_HALFS (BM * ASTR)
#define BS_HALFS (BK * BSTR)
#define STAGE_HALFS (AS_HALFS + BS_HALFS)
#define EPI_LDS 132
#define SMEM_PIPE ((size_t)(NSTAGE * STAGE_HALFS * 2))
#define SMEM_EPI  ((size_t)(BM * EPI_LDS * 4))
#define GEMM_SMEM_BYTES (SMEM_EPI > SMEM_PIPE ? SMEM_EPI : SMEM_PIPE)

__device__ __forceinline__ void hgemm_stage(
    const __half* __restrict__ A, const __half* __restrict__ W,
    int K, int N, int m0, int n0, int k0,
    __half* Asb, __half* Bsb, int tid)
{
    #pragma unroll
    for (int i = 0; i < 4; i++) {
        int c = tid + i * TPB;
        int row = c >> 2;
        int col8 = (c & 3) << 3;
        const __half* src = A + (size_t)(m0 + row) * K + k0 + col8;
        __pipeline_memcpy_async(Asb + row * ASTR + col8, src, 16);
    }
    #pragma unroll
    for (int i = 0; i < 4; i++) {
        int c = tid + i * TPB;
        int row = c >> 4;
        int col8 = (c & 15) << 3;
        __half* d = Bsb + row * BSTR + col8;
        if (n0 + col8 < N) {
            const __half* src = W + (size_t)(k0 + row) * N + n0 + col8;
            __pipeline_memcpy_async(d, src, 16);
        } else {
            *(float4*)d = make_float4(0.f, 0.f, 0.f, 0.f);
        }
    }
    __pipeline_commit();
}

template<int MODE>
__global__ __launch_bounds__(TPB) void hgemm_wmma(
    const __half* __restrict__ A, size_t aStride,
    const __half* __restrict__ W0, const __half* __restrict__ W1,
    const float* __restrict__ bias,
    float* __restrict__ Cf, __half* __restrict__ Ch, size_t outStride,
    int M, int N, int K, int ldc, int coff0, int coffStep)
{
    extern __shared__ __half smem[];

    const int tid  = threadIdx.x;
    const int wid  = tid >> 5;
    const int warp_m = wid & 1;
    const int warp_n = wid >> 1;
    const int m0 = blockIdx.y * BM;
    const int n0 = blockIdx.x * BN;
    const int z  = blockIdx.z;

    const __half* W = (z == 0) ? W0 : W1;
    A += (size_t)z * aStride;
    if (Cf) Cf += (size_t)z * outStride;
    if (Ch) Ch += (size_t)z * outStride;
    const int coff = coff0 + z * coffStep;

    wmma::fragment<wmma::accumulator, 16, 16, 16, float> cfr[4][4];
    #pragma unroll
    for (int i = 0; i < 4; i++) {
        #pragma unroll
        for (int j = 0; j < 4; j++) wmma::fill_fragment(cfr[i][j], 0.0f);
    }

    const int nK = K / BK;
    hgemm_stage(A, W, K, N, m0, n0, 0, smem, smem + AS_HALFS, tid);
    if (nK > 1) {
        __half* st = smem + STAGE_HALFS;
        hgemm_stage(A, W, K, N, m0, n0, BK, st, st + AS_HALFS, tid);
    }

    for (int kt = 0; kt < nK; kt++) {
        __pipeline_wait_prior(NSTAGE - 2);
        __syncthreads();
        if (kt + 2 < nK) {
            __half* st = smem + ((kt + 2) % NSTAGE) * STAGE_HALFS;
            hgemm_stage(A, W, K, N, m0, n0, (kt + 2) * BK, st, st + AS_HALFS, tid);
        }
        const __half* As = smem + (kt % NSTAGE) * STAGE_HALFS;
        const __half* Bs = As + AS_HALFS;

        #pragma unroll
        for (int kc = 0; kc < BK; kc += 16) {
            wmma::fragment<wmma::matrix_a, 16, 16, 16, __half, wmma::row_major> afr[4];
            wmma::fragment<wmma::matrix_b, 16, 16, 16, __half, wmma::row_major> bfr[4];
            #pragma unroll
            for (int i = 0; i < 4; i++) {
                wmma::load_matrix_sync(afr[i], As + (warp_m * 64 + i * 16) * ASTR + kc, ASTR);
            }
            #pragma unroll
            for (int j = 0; j < 4; j++) {
                wmma::load_matrix_sync(bfr[j], Bs + kc * BSTR + warp_n * 64 + j * 16, BSTR);
            }
            #pragma unroll
            for (int i = 0; i < 4; i++) {
                #pragma unroll
                for (int j = 0; j < 4; j++) {
                    wmma::mma_sync(cfr[i][j], afr[i], bfr[j], cfr[i][j]);
                }
            }
        }
    }

    if (MODE == 2) {
        __syncthreads();
        float* stg = (float*)smem;
        #pragma unroll
        for (int i = 0; i < 4; i++) {
            #pragma unroll
            for (int j = 0; j < 4; j++) {
                wmma::store_matrix_sync(stg + (warp_m * 64 + i * 16) * EPI_LDS + warp_n * 64 + j * 16,
                                        cfr[i][j], EPI_LDS, wmma::mem_row_major);
            }
        }
        __syncthreads();
        #pragma unroll
        for (int it = 0; it < 32; it++) {
            int q = tid + it * TPB;
            int r  = q >> 5;
            int c4 = (q & 31) << 2;
            int colb = n0 + c4;
            if (colb >= N) continue;
            float4 v = *(const float4*)(stg + r * EPI_LDS + c4);
            float r0 = gelu_exact(v.x + bias[colb + 0]);
            float r1 = gelu_exact(v.y + bias[colb + 1]);
            float r2 = gelu_exact(v.z + bias[colb + 2]);
            float r3 = gelu_exact(v.w + bias[colb + 3]);
            __half* dst = Ch + (size_t)(m0 + r) * ldc + coff + colb;
            ((__half2*)dst)[0] = __floats2half2_rn(r0, r1);
            ((__half2*)dst)[1] = __floats2half2_rn(r2, r3);
        }
    } else {
        #pragma unroll
        for (int i = 0; i < 4; i++) {
            #pragma unroll
            for (int j = 0; j < 4; j++) {
                int row = m0 + warp_m * 64 + i * 16;
                int col = n0 + warp_n * 64 + j * 16;
                if (MODE == 1) {
                    wmma::fragment<wmma::accumulator, 16, 16, 16, __half> hf;
                    #pragma unroll
                    for (int t = 0; t < hf.num_elements; t++) {
                        hf.x[t] = __float2half_rn(cfr[i][j].x[t]);
                    }
                    wmma::store_matrix_sync(Ch + (size_t)row * ldc + coff + col, hf, ldc, wmma::mem_row_major);
                } else {
                    wmma::store_matrix_sync(Cf + (size_t)row * ldc + coff + col, cfr[i][j], ldc, wmma::mem_row_major);
                }
            }
        }
    }
}

// ---------------- dt / dA (both directions) ----------------
__global__ void dtda_kernel(const __half* __restrict__ proj,
                            const float* __restrict__ dtb0, const float* __restrict__ dtb1,
                            const float* __restrict__ al0,  const float* __restrict__ al1,
                            float* __restrict__ dt, float* __restrict__ dA)
{
    int idx = blockIdx.x * blockDim.x + threadIdx.x;
    if (idx >= 2 * NTOK * NHEADS) return;
    int dir = idx / (NTOK * NHEADS);
    int rem = idx - dir * (NTOK * NHEADS);
    int h = rem % NHEADS;
    int j = rem / NHEADS;
    const float* dtb = dir ? dtb1 : dtb0;
    const float* al  = dir ? al1  : al0;
    float pv = __half2float(proj[(size_t)dir * NTOK * DPROJP + (size_t)j * DPROJP + (DINNER + CONVDIM) + h]);
    float raw = pv + dtb[h];
    float d = (raw > 20.f) ? raw : log1pf(expf(raw));
    float A = -expf(al[h]);
    dt[idx] = d;
    dA[idx] = expf(d * A);
}

// ---------------- depthwise conv + silu, 2 channels/thread -> fp16 ----------------
#define CONV2 (CONVDIM/2)
__global__ void conv_kernel(const __half* __restrict__ proj,
                            const float* __restrict__ cw0, const float* __restrict__ cw1,
                            const float* __restrict__ cb0, const float* __restrict__ cb1,
                            __half* __restrict__ out)
{
    int idx = blockIdx.x * blockDim.x + threadIdx.x;
    if (idx >= 2 * NTOK * CONV2) return;
    int dir = idx / (NTOK * CONV2);
    int rem = idx - dir * (NTOK * CONV2);
    int c2 = rem % CONV2;
    int row = rem / CONV2;
    int t = row % SEQ;
    int brow = row - t;
    int c = c2 * 2;
    const float* cw = dir ? cw1 : cw0;
    const float* cb = dir ? cb1 : cb0;
    const __half* pb = proj + (size_t)dir * NTOK * DPROJP;
    float acc0 = cb[c], acc1 = cb[c + 1];
    #pragma unroll
    for (int k = 0; k < DCONV; k++) {
        int tt = dir ? (t + (DCONV - 1) - k) : (t + k - (DCONV - 1));
        if (tt >= 0 && tt < SEQ) {
            __half2 pv = *(const __half2*)(pb + (size_t)(brow + tt) * DPROJP + DINNER + c);
            float2 p = __half22float2(pv);
            acc0 += cw[c * DCONV + k] * p.x;
            acc1 += cw[(c + 1) * DCONV + k] * p.y;
        }
    }
    __half2* ob = (__half2*)(out + (size_t)dir * NTOK * CONVDIM + (size_t)row * CONVDIM);
    ob[c2] = __floats2half2_rn(silu(acc0), silu(acc1));
}

// ---------------- selective scan: register-dense, 4 n-states/thread ----------------
// 256 threads per (dir,b,h). Thread layout: warp w handles p in [w*8, w*8+8);
// lane = ngroup*8 + (p&7); each thread owns n-states [ngroup*4, ngroup*4+4).
#define SCHUNK 64
__global__ __launch_bounds__(256) void scan_kernel(
    const __half* __restrict__ conv, const float* __restrict__ dt,
    const float* __restrict__ dA,
    const float* __restrict__ Dp0, const float* __restrict__ Dp1,
    __half* __restrict__ y)
{
    int unit = blockIdx.x;
    int dir = unit / (BATCH * NHEADS);
    int rem = unit - dir * (BATCH * NHEADS);
    int b = rem / NHEADS;
    int h = rem % NHEADS;
    int tid = threadIdx.x;
    int w = tid >> 5, lane = tid & 31;
    int p  = w * 8 + (lane & 7);
    int ng = lane >> 3;
    int n0 = ng * 4;
    int reverse = dir;

    const __half* convb = conv + (size_t)dir * NTOK * CONVDIM;
    const float* dtb   = dt   + (size_t)dir * NTOK * NHEADS;
    const float* dAb   = dA   + (size_t)dir * NTOK * NHEADS;
    __half* yb         = y    + (size_t)dir * NTOK * DINNER;
    const float Dv = dir ? Dp1[h] : Dp0[h];

    __shared__ __half sx[SCHUNK][HEADDIM];
    __shared__ float sB[SCHUNK][DSTATE];
    __shared__ float sC[SCHUNK][DSTATE];
    __shared__ float sdt[SCHUNK];
    __shared__ float sdA[SCHUNK];

    float hs0 = 0.f, hs1 = 0.f, hs2 = 0.f, hs3 = 0.f;

    for (int c0 = 0; c0 < SEQ; c0 += SCHUNK) {
        // x tile: 64 rows x 64 halves = 512 uint4 chunks; 256 threads x 2
        #pragma unroll
        for (int i = 0; i < 2; i++) {
            int q = tid + i * 256;
            int s = q >> 3, o = (q & 7) * 8;
            int t = reverse ? (SEQ - 1 - (c0 + s)) : (c0 + s);
            *(uint4*)&sx[s][o] = *(const uint4*)(convb + (size_t)(b * SEQ + t) * CONVDIM + h * HEADDIM + o);
        }
        // B+C tile: 64 rows x 32 halves (contiguous at DINNER) = 256 uint4; 1 per thread
        {
            int s = tid >> 2, o = (tid & 3) * 8;
            int t = reverse ? (SEQ - 1 - (c0 + s)) : (c0 + s);
            const __half* src = convb + (size_t)(b * SEQ + t) * CONVDIM + DINNER + o;
            #pragma unroll
            for (int k = 0; k < 8; k++) {
                float v = __half2float(src[k]);
                int idx = o + k;
                if (idx < DSTATE) sB[s][idx] = v;
                else              sC[s][idx - DSTATE] = v;
            }
        }
        if (tid < SCHUNK) {
            int t = reverse ? (SEQ - 1 - (c0 + tid)) : (c0 + tid);
            sdt[tid] = dtb[(size_t)(b * SEQ + t) * NHEADS + h];
            sdA[tid] = dAb[(size_t)(b * SEQ + t) * NHEADS + h];
        }
        __syncthreads();

        #pragma unroll 4
        for (int s = 0; s < SCHUNK; s++) {
            float dAv = sdA[s], dtv = sdt[s];
            float x = __half2float(sx[s][p]);
            float dtx = dtv * x;
            float4 B4 = *(const float4*)&sB[s][n0];
            float4 C4 = *(const float4*)&sC[s][n0];
            hs0 = hs0 * dAv + dtx * B4.x;
            hs1 = hs1 * dAv + dtx * B4.y;
            hs2 = hs2 * dAv + dtx * B4.z;
            hs3 = hs3 * dAv + dtx * B4.w;
            float yv = hs0 * C4.x + hs1 * C4.y + hs2 * C4.z + hs3 * C4.w;
            yv += __shfl_xor_sync(0xffffffffu, yv, 8);
            yv += __shfl_xor_sync(0xffffffffu, yv, 16);
            if (ng == 0) {
                int t = reverse ? (SEQ - 1 - (c0 + s)) : (c0 + s);
                yb[(size_t)(b * SEQ + t) * DINNER + h * HEADDIM + p] = __float2half_rn(yv + Dv * x);
            }
        }
        __syncthreads();
    }
}

// ---------------- gate (y * silu(z)) + grouped RMSNorm -> fp16 (both dirs) ----------------
__global__ __launch_bounds__(256) void gate_rmsnorm_kernel(
    const __half* __restrict__ proj, const __half* __restrict__ y_in,
    const float* __restrict__ nw0, const float* __restrict__ nw1,
    __half* __restrict__ y_out)
{
    int dir = blockIdx.x >> 13;
    int row = blockIdx.x & (NTOK - 1);
    int tid = threadIdx.x;
    const __half2* pb = (const __half2*)(proj + (size_t)dir * NTOK * DPROJP + (size_t)row * DPROJP);
    const __half2* yb = (const __half2*)(y_in + (size_t)dir * NTOK * DINNER + (size_t)row * DINNER);
    __half2* ob       = (__half2*)(y_out + (size_t)dir * NTOK * DINNER + (size_t)row * DINNER);
    const float* nw  = dir ? nw1 : nw0;

    float v[6];
    float ss = 0.f;
    #pragma unroll
    for (int i = 0; i < 3; i++) {
        int c2 = tid + i * 256;          // half2 index over 768
        float2 z  = __half22float2(pb[c2]);
        float2 yv = __half22float2(yb[c2]);
        float t0 = yv.x * silu(z.x);
        float t1 = yv.y * silu(z.y);
        v[i * 2 + 0] = t0; v[i * 2 + 1] = t1;
        ss += t0 * t0 + t1 * t1;
    }
    float tot = block_reduce_sum(ss);
    float rs = rsqrtf(tot * (1.0f / DINNER) + 1e-5f);
    #pragma unroll
    for (int i = 0; i < 3; i++) {
        int c2 = tid + i * 256;
        float r0 = v[i * 2 + 0] * rs * nw[c2 * 2 + 0];
        float r1 = v[i * 2 + 1] * rs * nw[c2 * 2 + 1];
        ob[c2] = __floats2half2_rn(r0, r1);
    }
}

// ---------------- host-side input binding by element count ----------------
static const float* pick(void* const* d_in, const int* sz, int n_in, int count, int occ) {
    int seen = 0;
    for (int i = 0; i < n_in; i++) {
        if (sz[i] == count) {
            if (seen == occ) return (const float*)d_in[i];
            seen++;
        }
    }
    return nullptr;
}

extern "C" void kernel_launch(void* const* d_in, const int* in_sizes, int n_in,
                              void* d_out, int out_size)
{
    const float* x      = pick(d_in, in_sizes, n_in, NTOK * DMODEL, 0);
    const float* ln1_w  = pick(d_in, in_sizes, n_in, 768, 0);
    const float* ln1_b  = pick(d_in, in_sizes, n_in, 768, 1);
    const float* ln2_w  = pick(d_in, in_sizes, n_in, 768, 2);
    const float* ln2_b  = pick(d_in, in_sizes, n_in, 768, 3);
    const float* ffn_b2 = pick(d_in, in_sizes, n_in, 768, 4);
    const float* ffn_w1 = pick(d_in, in_sizes, n_in, DINNER * DFFN, 0);
    const float* ffn_b1 = pick(d_in, in_sizes, n_in, DFFN, 0);
    const float* ffn_w2 = pick(d_in, in_sizes, n_in, DFFN * DMODEL, 0);

    const float* in_w0    = pick(d_in, in_sizes, n_in, DMODEL * DPROJ, 0);
    const float* in_w1    = pick(d_in, in_sizes, n_in, DMODEL * DPROJ, 1);
    const float* conv_w0  = pick(d_in, in_sizes, n_in, CONVDIM * DCONV, 0);
    const float* conv_w1  = pick(d_in, in_sizes, n_in, CONVDIM * DCONV, 1);
    const float* conv_b0  = pick(d_in, in_sizes, n_in, CONVDIM, 0);
    const float* conv_b1  = pick(d_in, in_sizes, n_in, CONVDIM, 1);
    const float* dt_bias0 = pick(d_in, in_sizes, n_in, NHEADS, 0);
    const float* dt_bias1 = pick(d_in, in_sizes, n_in, NHEADS, 3);
    const float* A_log0   = pick(d_in, in_sizes, n_in, NHEADS, 1);
    const float* A_log1   = pick(d_in, in_sizes, n_in, NHEADS, 4);
    const float* Dp0      = pick(d_in, in_sizes, n_in, NHEADS, 2);
    const float* Dp1      = pick(d_in, in_sizes, n_in, NHEADS, 5);
    const float* norm_w0  = pick(d_in, in_sizes, n_in, DINNER, 0);
    const float* norm_w1  = pick(d_in, in_sizes, n_in, DINNER, 1);
    const float* out_w0   = pick(d_in, in_sizes, n_in, DINNER * DMODEL, 0);
    const float* out_w1   = pick(d_in, in_sizes, n_in, DINNER * DMODEL, 1);

    __half* p_proj = 0; cudaGetSymbolAddress((void**)&p_proj, h_proj);
    __half* p_conv = 0; cudaGetSymbolAddress((void**)&p_conv, h_conv);
    float* p_dt   = 0;  cudaGetSymbolAddress((void**)&p_dt,   g_dt);
    float* p_dA   = 0;  cudaGetSymbolAddress((void**)&p_dA,   g_dA);
    __half* p_y   = 0;  cudaGetSymbolAddress((void**)&p_y,    h_y);
    float* p_h2   = 0;  cudaGetSymbolAddress((void**)&p_h2,   g_h2);

    __half* ph_xn  = 0; cudaGetSymbolAddress((void**)&ph_xn,  h_xn);
    __half* ph_yg  = 0; cudaGetSymbolAddress((void**)&ph_yg,  h_yg);
    __half* ph_bi  = 0; cudaGetSymbolAddress((void**)&ph_bi,  h_bi);
    __half* ph_ffn = 0; cudaGetSymbolAddress((void**)&ph_ffn, h_ffn);

    __half* pw_in0  = 0; cudaGetSymbolAddress((void**)&pw_in0,  hw_in0);
    __half* pw_in1  = 0; cudaGetSymbolAddress((void**)&pw_in1,  hw_in1);
    __half* pw_out0 = 0; cudaGetSymbolAddress((void**)&pw_out0, hw_out0);
    __half* pw_out1 = 0; cudaGetSymbolAddress((void**)&pw_out1, hw_out1);
    __half* pw_f1   = 0; cudaGetSymbolAddress((void**)&pw_f1,   hw_f1);
    __half* pw_f2   = 0; cudaGetSymbolAddress((void**)&pw_f2,   hw_f2);

    cudaFuncSetAttribute(hgemm_wmma<0>, cudaFuncAttributeMaxDynamicSharedMemorySize, GEMM_SMEM_BYTES);
    cudaFuncSetAttribute(hgemm_wmma<1>, cudaFuncAttributeMaxDynamicSharedMemorySize, GEMM_SMEM_BYTES);
    cudaFuncSetAttribute(hgemm_wmma<2>, cudaFuncAttributeMaxDynamicSharedMemorySize, GEMM_SMEM_BYTES);

    float* out = (float*)d_out;
    const int T = 256;

    // 1) merged weight conversion fp32 -> fp16 (single launch)
    f2h_all_kernel<<<(F2H_TOT + T - 1) / T, T>>>(
        in_w0, in_w1, out_w0, out_w1, ffn_w1, ffn_w2,
        pw_in0, pw_in1, pw_out0, pw_out1, pw_f1, pw_f2);

    // 2) LN1 -> fp16
    layernorm_kernel<<<NTOK, 256>>>(x, nullptr, nullptr, ln1_w, ln1_b, nullptr, ph_xn, 0);

    // 3) in_proj both dirs (z-batched) -> fp16 proj
    {
        dim3 grid((DPROJ + BN - 1) / BN, NTOK / BM, 2);
        hgemm_wmma<1><<<grid, TPB, GEMM_SMEM_BYTES>>>(
            ph_xn, 0, pw_in0, pw_in1, nullptr,
            nullptr, p_proj, (size_t)NTOK * DPROJP,
            NTOK, DPROJ, DMODEL, DPROJP, 0, 0);
    }
    // 4) dt/dA both dirs
    dtda_kernel<<<(2 * NTOK * NHEADS + T - 1) / T, T>>>(p_proj, dt_bias0, dt_bias1, A_log0, A_log1, p_dt, p_dA);
    // 5) conv both dirs -> fp16
    conv_kernel<<<(2 * NTOK * CONV2 + T - 1) / T, T>>>(p_proj, conv_w0, conv_w1, conv_b0, conv_b1, p_conv);
    // 6) scan both dirs (192 CTAs x 256 threads, register-dense) -> fp16 y
    scan_kernel<<<2 * BATCH * NHEADS, 256>>>(p_conv, p_dt, p_dA, Dp0, Dp1, p_y);
    // 7) gate + rmsnorm both dirs -> fp16
    gate_rmsnorm_kernel<<<2 * NTOK, 256>>>(p_proj, p_y, norm_w0, norm_w1, ph_yg);
    // 8) out_proj both dirs (z-batched) -> fp16 concat buffer
    {
        dim3 grid(DMODEL / BN, NTOK / BM, 2);
        hgemm_wmma<1><<<grid, TPB, GEMM_SMEM_BYTES>>>(
            ph_yg, (size_t)NTOK * DINNER, pw_out0, pw_out1, nullptr,
            nullptr, ph_bi, 0,
            NTOK, DMODEL, DINNER, DINNER, 0, DMODEL);
    }
    // 9) FFN1 with fused bias+gelu -> fp16
    {
        dim3 grid(DFFN / BN, NTOK / BM, 1);
        hgemm_wmma<2><<<grid, TPB, GEMM_SMEM_BYTES>>>(
            ph_bi, 0, pw_f1, pw_f1, ffn_b1,
            nullptr, ph_ffn, 0,
            NTOK, DFFN, DINNER, DFFN, 0, 0);
    }
    // 10) FFN2 -> fp32 raw
    {
        dim3 grid(DMODEL / BN, NTOK / BM, 1);
        hgemm_wmma<0><<<grid, TPB, GEMM_SMEM_BYTES>>>(
            ph_ffn, 0, pw_f2, pw_f2, nullptr,
            p_h2, nullptr, 0,
            NTOK, DMODEL, DFFN, DMODEL, 0, 0);
    }
    // 11) out = LN2(x + gelu(h2 + b2))
    layernorm_kernel<<<NTOK, 256>>>(x, p_h2, ffn_b2, ln2_w, ln2_b, out, nullptr, 1);
}

// round 14
// speedup vs baseline: 1.2646x; 1.0023x over previous
#include <cuda_runtime.h>
#include <cuda_fp16.h>
#include <cuda_pipeline.h>
#include <mma.h>
#include <math.h>

using namespace nvcuda;

// ---------------- problem constants ----------------
#define BATCH   4
#define SEQ     2048
#define DMODEL  768
#define DSTATE  16
#define DCONV   4
#define HEADDIM 64
#define DINNER  1536
#define NHEADS  24
#define CONVDIM 1568
#define DPROJ   3128
#define DPROJP  3328
#define NTOK    (BATCH*SEQ)
#define DFFN    3072

// ---------------- scratch (device globals; no allocation allowed) ----------------
__device__ __half h_proj[(size_t)2*NTOK*DPROJP];
__device__ __half h_conv[(size_t)2*NTOK*CONVDIM];
__device__ float  g_dt  [(size_t)2*NTOK*NHEADS];
__device__ float  g_dA  [(size_t)2*NTOK*NHEADS];
__device__ __half h_y   [(size_t)2*NTOK*DINNER];
__device__ __half h_yg  [(size_t)2*NTOK*DINNER];
__device__ float  g_h2  [(size_t)NTOK*DMODEL];

__device__ __half h_xn [(size_t)NTOK*DMODEL];
__device__ __half h_bi [(size_t)NTOK*DINNER];
__device__ __half h_ffn[(size_t)NTOK*DFFN];

// fp16 weight buffers
__device__ __half hw_in0 [(size_t)DMODEL*DPROJ];
__device__ __half hw_in1 [(size_t)DMODEL*DPROJ];
__device__ __half hw_out0[(size_t)DINNER*DMODEL];
__device__ __half hw_out1[(size_t)DINNER*DMODEL];
__device__ __half hw_f1  [(size_t)DINNER*DFFN];
__device__ __half hw_f2  [(size_t)DFFN*DMODEL];

// ---------------- helpers ----------------
__device__ __forceinline__ float gelu_exact(float x) {
    return 0.5f * x * (1.0f + erff(x * 0.70710678118654752f));
}
__device__ __forceinline__ float silu(float x) {
    return x / (1.0f + expf(-x));
}

__device__ float block_reduce_sum(float v) {
    __shared__ float sh[32];
    __shared__ float tot;
    int lane = threadIdx.x & 31, wid = threadIdx.x >> 5;
    #pragma unroll
    for (int m = 16; m >= 1; m >>= 1) v += __shfl_xor_sync(0xffffffffu, v, m);
    if (lane == 0) sh[wid] = v;
    __syncthreads();
    int nw = blockDim.x >> 5;
    v = (threadIdx.x < nw) ? sh[threadIdx.x] : 0.f;
    if (wid == 0) {
        #pragma unroll
        for (int m = 16; m >= 1; m >>= 1) v += __shfl_xor_sync(0xffffffffu, v, m);
        if (lane == 0) tot = v;
    }
    __syncthreads();
    return tot;
}

// ---------------- merged fp32 -> fp16 conversion for all 6 weights ----------------
#define N4_IN  (DMODEL*DPROJ/4)
#define N4_OUT (DINNER*DMODEL/4)
#define N4_F1  (DINNER*DFFN/4)
#define N4_F2  (DFFN*DMODEL/4)
#define F2H_B0 (N4_IN)
#define F2H_B1 (2*N4_IN)
#define F2H_B2 (2*N4_IN + N4_OUT)
#define F2H_B3 (2*N4_IN + 2*N4_OUT)
#define F2H_B4 (2*N4_IN + 2*N4_OUT + N4_F1)
#define F2H_TOT (2*N4_IN + 2*N4_OUT + N4_F1 + N4_F2)

__global__ void f2h_all_kernel(
    const float* __restrict__ s0, const float* __restrict__ s1,
    const float* __restrict__ s2, const float* __restrict__ s3,
    const float* __restrict__ s4, const float* __restrict__ s5,
    __half* __restrict__ d0, __half* __restrict__ d1,
    __half* __restrict__ d2, __half* __restrict__ d3,
    __half* __restrict__ d4, __half* __restrict__ d5)
{
    int i = blockIdx.x * blockDim.x + threadIdx.x;
    if (i >= F2H_TOT) return;
    const float* src;
    __half* dst;
    int j;
    if (i < F2H_B0)      { src = s0; dst = d0; j = i; }
    else if (i < F2H_B1) { src = s1; dst = d1; j = i - F2H_B0; }
    else if (i < F2H_B2) { src = s2; dst = d2; j = i - F2H_B1; }
    else if (i < F2H_B3) { src = s3; dst = d3; j = i - F2H_B2; }
    else if (i < F2H_B4) { src = s4; dst = d4; j = i - F2H_B3; }
    else                 { src = s5; dst = d5; j = i - F2H_B4; }
    float4 v = ((const float4*)src)[j];
    ((__half2*)dst)[j * 2 + 0] = __floats2half2_rn(v.x, v.y);
    ((__half2*)dst)[j * 2 + 1] = __floats2half2_rn(v.z, v.w);
}

// ---------------- layernorm (cols = 768) ----------------
__global__ __launch_bounds__(256) void layernorm_kernel(
    const float* __restrict__ x, const float* __restrict__ add,
    const float* __restrict__ addb,
    const float* __restrict__ w, const float* __restrict__ b,
    float* __restrict__ out, __half* __restrict__ outh, int mode)
{
    int row = blockIdx.x;
    int tid = threadIdx.x;
    const size_t base = (size_t)row * DMODEL;
    float v[3];
    float s = 0.f;
    #pragma unroll
    for (int i = 0; i < 3; i++) {
        int c = tid + i * 256;
        float t = x[base + c];
        if (mode == 1) t += gelu_exact(add[base + c] + addb[c]);
        v[i] = t; s += t;
    }
    float mean = block_reduce_sum(s) * (1.0f / DMODEL);
    float sq = 0.f;
    #pragma unroll
    for (int i = 0; i < 3; i++) { float d = v[i] - mean; sq += d * d; }
    float var = block_reduce_sum(sq) * (1.0f / DMODEL);
    float rstd = rsqrtf(var + 1e-5f);
    #pragma unroll
    for (int i = 0; i < 3; i++) {
        int c = tid + i * 256;
        float r = (v[i] - mean) * rstd * w[c] + b[c];
        if (out)  out[base + c] = r;
        if (outh) outh[base + c] = __float2half_rn(r);
    }
}

// ---------------- WMMA HGEMM: CTA 128x128, 4 warps of 64x64, BK=32, 3-stage ----------------
// MODE 0: fp32 raw -> Cf ; MODE 1: fp16 raw -> Ch ; MODE 2: bias+gelu -> fp16 Ch
#define BM 128
#define BN 128
#define BK 32
#define TPB 128
#define NSTAGE 3
#define ASTR 40
#define BSTR 136
#define AS_HALFS (BM * ASTR)
#define BS_HALFS (BK * BSTR)
#define STAGE_HALFS (AS_HALFS + BS_HALFS)
#define EPI_LDS 132
#define SMEM_PIPE ((size_t)(NSTAGE * STAGE_HALFS * 2))
#define SMEM_EPI  ((size_t)(BM * EPI_LDS * 4))
#define GEMM_SMEM_BYTES (SMEM_EPI > SMEM_PIPE ? SMEM_EPI : SMEM_PIPE)

__device__ __forceinline__ void hgemm_stage(
    const __half* __restrict__ A, const __half* __restrict__ W,
    int K, int N, int m0, int n0, int k0,
    __half* Asb, __half* Bsb, int tid)
{
    #pragma unroll
    for (int i = 0; i < 4; i++) {
        int c = tid + i * TPB;
        int row = c >> 2;
        int col8 = (c & 3) << 3;
        const __half* src = A + (size_t)(m0 + row) * K + k0 + col8;
        __pipeline_memcpy_async(Asb + row * ASTR + col8, src, 16);
    }
    #pragma unroll
    for (int i = 0; i < 4; i++) {
        int c = tid + i * TPB;
        int row = c >> 4;
        int col8 = (c & 15) << 3;
        __half* d = Bsb + row * BSTR + col8;
        if (n0 + col8 < N) {
            const __half* src = W + (size_t)(k0 + row) * N + n0 + col8;
            __pipeline_memcpy_async(d, src, 16);
        } else {
            *(float4*)d = make_float4(0.f, 0.f, 0.f, 0.f);
        }
    }
    __pipeline_commit();
}

template<int MODE>
__global__ __launch_bounds__(TPB) void hgemm_wmma(
    const __half* __restrict__ A, size_t aStride,
    const __half* __restrict__ W0, const __half* __restrict__ W1,
    const float* __restrict__ bias,
    float* __restrict__ Cf, __half* __restrict__ Ch, size_t outStride,
    int M, int N, int K, int ldc, int coff0, int coffStep)
{
    extern __shared__ __half smem[];

    const int tid  = threadIdx.x;
    const int wid  = tid >> 5;
    const int warp_m = wid & 1;
    const int warp_n = wid >> 1;
    const int m0 = blockIdx.y * BM;
    const int n0 = blockIdx.x * BN;
    const int z  = blockIdx.z;

    const __half* W = (z == 0) ? W0 : W1;
    A += (size_t)z * aStride;
    if (Cf) Cf += (size_t)z * outStride;
    if (Ch) Ch += (size_t)z * outStride;
    const int coff = coff0 + z * coffStep;

    wmma::fragment<wmma::accumulator, 16, 16, 16, float> cfr[4][4];
    #pragma unroll
    for (int i = 0; i < 4; i++) {
        #pragma unroll
        for (int j = 0; j < 4; j++) wmma::fill_fragment(cfr[i][j], 0.0f);
    }

    const int nK = K / BK;
    hgemm_stage(A, W, K, N, m0, n0, 0, smem, smem + AS_HALFS, tid);
    if (nK > 1) {
        __half* st = smem + STAGE_HALFS;
        hgemm_stage(A, W, K, N, m0, n0, BK, st, st + AS_HALFS, tid);
    }

    for (int kt = 0; kt < nK; kt++) {
        __pipeline_wait_prior(NSTAGE - 2);
        __syncthreads();
        if (kt + 2 < nK) {
            __half* st = smem + ((kt + 2) % NSTAGE) * STAGE_HALFS;
            hgemm_stage(A, W, K, N, m0, n0, (kt + 2) * BK, st, st + AS_HALFS, tid);
        }
        const __half* As = smem + (kt % NSTAGE) * STAGE_HALFS;
        const __half* Bs = As + AS_HALFS;

        #pragma unroll
        for (int kc = 0; kc < BK; kc += 16) {
            wmma::fragment<wmma::matrix_a, 16, 16, 16, __half, wmma::row_major> afr[4];
            wmma::fragment<wmma::matrix_b, 16, 16, 16, __half, wmma::row_major> bfr[4];
            #pragma unroll
            for (int i = 0; i < 4; i++) {
                wmma::load_matrix_sync(afr[i], As + (warp_m * 64 + i * 16) * ASTR + kc, ASTR);
            }
            #pragma unroll
            for (int j = 0; j < 4; j++) {
                wmma::load_matrix_sync(bfr[j], Bs + kc * BSTR + warp_n * 64 + j * 16, BSTR);
            }
            #pragma unroll
            for (int i = 0; i < 4; i++) {
                #pragma unroll
                for (int j = 0; j < 4; j++) {
                    wmma::mma_sync(cfr[i][j], afr[i], bfr[j], cfr[i][j]);
                }
            }
        }
    }

    if (MODE == 2) {
        __syncthreads();
        float* stg = (float*)smem;
        #pragma unroll
        for (int i = 0; i < 4; i++) {
            #pragma unroll
            for (int j = 0; j < 4; j++) {
                wmma::store_matrix_sync(stg + (warp_m * 64 + i * 16) * EPI_LDS + warp_n * 64 + j * 16,
                                        cfr[i][j], EPI_LDS, wmma::mem_row_major);
            }
        }
        __syncthreads();
        #pragma unroll
        for (int it = 0; it < 32; it++) {
            int q = tid + it * TPB;
            int r  = q >> 5;
            int c4 = (q & 31) << 2;
            int colb = n0 + c4;
            if (colb >= N) continue;
            float4 v = *(const float4*)(stg + r * EPI_LDS + c4);
            float r0 = gelu_exact(v.x + bias[colb + 0]);
            float r1 = gelu_exact(v.y + bias[colb + 1]);
            float r2 = gelu_exact(v.z + bias[colb + 2]);
            float r3 = gelu_exact(v.w + bias[colb + 3]);
            __half* dst = Ch + (size_t)(m0 + r) * ldc + coff + colb;
            ((__half2*)dst)[0] = __floats2half2_rn(r0, r1);
            ((__half2*)dst)[1] = __floats2half2_rn(r2, r3);
        }
    } else {
        #pragma unroll
        for (int i = 0; i < 4; i++) {
            #pragma unroll
            for (int j = 0; j < 4; j++) {
                int row = m0 + warp_m * 64 + i * 16;
                int col = n0 + warp_n * 64 + j * 16;
                if (MODE == 1) {
                    wmma::fragment<wmma::accumulator, 16, 16, 16, __half> hf;
                    #pragma unroll
                    for (int t = 0; t < hf.num_elements; t++) {
                        hf.x[t] = __float2half_rn(cfr[i][j].x[t]);
                    }
                    wmma::store_matrix_sync(Ch + (size_t)row * ldc + coff + col, hf, ldc, wmma::mem_row_major);
                } else {
                    wmma::store_matrix_sync(Cf + (size_t)row * ldc + coff + col, cfr[i][j], ldc, wmma::mem_row_major);
                }
            }
        }
    }
}

// ---------------- dt / dA (both directions) ----------------
__global__ void dtda_kernel(const __half* __restrict__ proj,
                            const float* __restrict__ dtb0, const float* __restrict__ dtb1,
                            const float* __restrict__ al0,  const float* __restrict__ al1,
                            float* __restrict__ dt, float* __restrict__ dA)
{
    int idx = blockIdx.x * blockDim.x + threadIdx.x;
    if (idx >= 2 * NTOK * NHEADS) return;
    int dir = idx / (NTOK * NHEADS);
    int rem = idx - dir * (NTOK * NHEADS);
    int h = rem % NHEADS;
    int j = rem / NHEADS;
    const float* dtb = dir ? dtb1 : dtb0;
    const float* al  = dir ? al1  : al0;
    float pv = __half2float(proj[(size_t)dir * NTOK * DPROJP + (size_t)j * DPROJP + (DINNER + CONVDIM) + h]);
    float raw = pv + dtb[h];
    float d = (raw > 20.f) ? raw : log1pf(expf(raw));
    float A = -expf(al[h]);
    dt[idx] = d;
    dA[idx] = expf(d * A);
}

// ---------------- depthwise conv + silu, 2 channels/thread -> fp16 ----------------
#define CONV2 (CONVDIM/2)
__global__ void conv_kernel(const __half* __restrict__ proj,
                            const float* __restrict__ cw0, const float* __restrict__ cw1,
                            const float* __restrict__ cb0, const float* __restrict__ cb1,
                            __half* __restrict__ out)
{
    int idx = blockIdx.x * blockDim.x + threadIdx.x;
    if (idx >= 2 * NTOK * CONV2) return;
    int dir = idx / (NTOK * CONV2);
    int rem = idx - dir * (NTOK * CONV2);
    int c2 = rem % CONV2;
    int row = rem / CONV2;
    int t = row % SEQ;
    int brow = row - t;
    int c = c2 * 2;
    const float* cw = dir ? cw1 : cw0;
    const float* cb = dir ? cb1 : cb0;
    const __half* pb = proj + (size_t)dir * NTOK * DPROJP;
    float acc0 = cb[c], acc1 = cb[c + 1];
    #pragma unroll
    for (int k = 0; k < DCONV; k++) {
        int tt = dir ? (t + (DCONV - 1) - k) : (t + k - (DCONV - 1));
        if (tt >= 0 && tt < SEQ) {
            __half2 pv = *(const __half2*)(pb + (size_t)(brow + tt) * DPROJP + DINNER + c);
            float2 p = __half22float2(pv);
            acc0 += cw[c * DCONV + k] * p.x;
            acc1 += cw[(c + 1) * DCONV + k] * p.y;
        }
    }
    __half2* ob = (__half2*)(out + (size_t)dir * NTOK * CONVDIM + (size_t)row * CONVDIM);
    ob[c2] = __floats2half2_rn(silu(acc0), silu(acc1));
}

// ---------------- selective scan: register-dense, 4 n-states/thread ----------------
// 256 threads per (dir,b,h). Thread layout: warp w handles p in [w*8, w*8+8);
// lane = ngroup*8 + (p&7); each thread owns n-states [ngroup*4, ngroup*4+4).
#define SCHUNK 64
__global__ __launch_bounds__(256) void scan_kernel(
    const __half* __restrict__ conv, const float* __restrict__ dt,
    const float* __restrict__ dA,
    const float* __restrict__ Dp0, const float* __restrict__ Dp1,
    __half* __restrict__ y)
{
    int unit = blockIdx.x;
    int dir = unit / (BATCH * NHEADS);
    int rem = unit - dir * (BATCH * NHEADS);
    int b = rem / NHEADS;
    int h = rem % NHEADS;
    int tid = threadIdx.x;
    int w = tid >> 5, lane = tid & 31;
    int p  = w * 8 + (lane & 7);
    int ng = lane >> 3;
    int n0 = ng * 4;
    int reverse = dir;

    const __half* convb = conv + (size_t)dir * NTOK * CONVDIM;
    const float* dtb   = dt   + (size_t)dir * NTOK * NHEADS;
    const float* dAb   = dA   + (size_t)dir * NTOK * NHEADS;
    __half* yb         = y    + (size_t)dir * NTOK * DINNER;
    const float Dv = dir ? Dp1[h] : Dp0[h];

    __shared__ __half sx[SCHUNK][HEADDIM];
    __shared__ float sB[SCHUNK][DSTATE];
    __shared__ float sC[SCHUNK][DSTATE];
    __shared__ float sdt[SCHUNK];
    __shared__ float sdA[SCHUNK];

    float hs0 = 0.f, hs1 = 0.f, hs2 = 0.f, hs3 = 0.f;

    for (int c0 = 0; c0 < SEQ; c0 += SCHUNK) {
        // x tile: 64 rows x 64 halves = 512 uint4 chunks; 256 threads x 2
        #pragma unroll
        for (int i = 0; i < 2; i++) {
            int q = tid + i * 256;
            int s = q >> 3, o = (q & 7) * 8;
            int t = reverse ? (SEQ - 1 - (c0 + s)) : (c0 + s);
            *(uint4*)&sx[s][o] = *(const uint4*)(convb + (size_t)(b * SEQ + t) * CONVDIM + h * HEADDIM + o);
        }
        // B+C tile: 64 rows x 32 halves (contiguous at DINNER) = 256 uint4; 1 per thread
        {
            int s = tid >> 2, o = (tid & 3) * 8;
            int t = reverse ? (SEQ - 1 - (c0 + s)) : (c0 + s);
            const __half* src = convb + (size_t)(b * SEQ + t) * CONVDIM + DINNER + o;
            #pragma unroll
            for (int k = 0; k < 8; k++) {
                float v = __half2float(src[k]);
                int idx = o + k;
                if (idx < DSTATE) sB[s][idx] = v;
                else              sC[s][idx - DSTATE] = v;
            }
        }
        if (tid < SCHUNK) {
            int t = reverse ? (SEQ - 1 - (c0 + tid)) : (c0 + tid);
            sdt[tid] = dtb[(size_t)(b * SEQ + t) * NHEADS + h];
            sdA[tid] = dAb[(size_t)(b * SEQ + t) * NHEADS + h];
        }
        __syncthreads();

        #pragma unroll 4
        for (int s = 0; s < SCHUNK; s++) {
            float dAv = sdA[s], dtv = sdt[s];
            float x = __half2float(sx[s][p]);
            float dtx = dtv * x;
            float4 B4 = *(const float4*)&sB[s][n0];
            float4 C4 = *(const float4*)&sC[s][n0];
            hs0 = hs0 * dAv + dtx * B4.x;
            hs1 = hs1 * dAv + dtx * B4.y;
            hs2 = hs2 * dAv + dtx * B4.z;
            hs3 = hs3 * dAv + dtx * B4.w;
            float yv = hs0 * C4.x + hs1 * C4.y + hs2 * C4.z + hs3 * C4.w;
            yv += __shfl_xor_sync(0xffffffffu, yv, 8);
            yv += __shfl_xor_sync(0xffffffffu, yv, 16);
            if (ng == 0) {
                int t = reverse ? (SEQ - 1 - (c0 + s)) : (c0 + s);
                yb[(size_t)(b * SEQ + t) * DINNER + h * HEADDIM + p] = __float2half_rn(yv + Dv * x);
            }
        }
        __syncthreads();
    }
}

// ---------------- gate (y * silu(z)) + grouped RMSNorm -> fp16 (both dirs) ----------------
__global__ __launch_bounds__(256) void gate_rmsnorm_kernel(
    const __half* __restrict__ proj, const __half* __restrict__ y_in,
    const float* __restrict__ nw0, const float* __restrict__ nw1,
    __half* __restrict__ y_out)
{
    int dir = blockIdx.x >> 13;
    int row = blockIdx.x & (NTOK - 1);
    int tid = threadIdx.x;
    const __half2* pb = (const __half2*)(proj + (size_t)dir * NTOK * DPROJP + (size_t)row * DPROJP);
    const __half2* yb = (const __half2*)(y_in + (size_t)dir * NTOK * DINNER + (size_t)row * DINNER);
    __half2* ob       = (__half2*)(y_out + (size_t)dir * NTOK * DINNER + (size_t)row * DINNER);
    const float* nw  = dir ? nw1 : nw0;

    float v[6];
    float ss = 0.f;
    #pragma unroll
    for (int i = 0; i < 3; i++) {
        int c2 = tid + i * 256;          // half2 index over 768
        float2 z  = __half22float2(pb[c2]);
        float2 yv = __half22float2(yb[c2]);
        float t0 = yv.x * silu(z.x);
        float t1 = yv.y * silu(z.y);
        v[i * 2 + 0] = t0; v[i * 2 + 1] = t1;
        ss += t0 * t0 + t1 * t1;
    }
    float tot = block_reduce_sum(ss);
    float rs = rsqrtf(tot * (1.0f / DINNER) + 1e-5f);
    #pragma unroll
    for (int i = 0; i < 3; i++) {
        int c2 = tid + i * 256;
        float r0 = v[i * 2 + 0] * rs * nw[c2 * 2 + 0];
        float r1 = v[i * 2 + 1] * rs * nw[c2 * 2 + 1];
        ob[c2] = __floats2half2_rn(r0, r1);
    }
}

// ---------------- host-side input binding by element count ----------------
static const float* pick(void* const* d_in, const int* sz, int n_in, int count, int occ) {
    int seen = 0;
    for (int i = 0; i < n_in; i++) {
        if (sz[i] == count) {
            if (seen == occ) return (const float*)d_in[i];
            seen++;
        }
    }
    return nullptr;
}

extern "C" void kernel_launch(void* const* d_in, const int* in_sizes, int n_in,
                              void* d_out, int out_size)
{
    const float* x      = pick(d_in, in_sizes, n_in, NTOK * DMODEL, 0);
    const float* ln1_w  = pick(d_in, in_sizes, n_in, 768, 0);
    const float* ln1_b  = pick(d_in, in_sizes, n_in, 768, 1);
    const float* ln2_w  = pick(d_in, in_sizes, n_in, 768, 2);
    const float* ln2_b  = pick(d_in, in_sizes, n_in, 768, 3);
    const float* ffn_b2 = pick(d_in, in_sizes, n_in, 768, 4);
    const float* ffn_w1 = pick(d_in, in_sizes, n_in, DINNER * DFFN, 0);
    const float* ffn_b1 = pick(d_in, in_sizes, n_in, DFFN, 0);
    const float* ffn_w2 = pick(d_in, in_sizes, n_in, DFFN * DMODEL, 0);

    const float* in_w0    = pick(d_in, in_sizes, n_in, DMODEL * DPROJ, 0);
    const float* in_w1    = pick(d_in, in_sizes, n_in, DMODEL * DPROJ, 1);
    const float* conv_w0  = pick(d_in, in_sizes, n_in, CONVDIM * DCONV, 0);
    const float* conv_w1  = pick(d_in, in_sizes, n_in, CONVDIM * DCONV, 1);
    const float* conv_b0  = pick(d_in, in_sizes, n_in, CONVDIM, 0);
    const float* conv_b1  = pick(d_in, in_sizes, n_in, CONVDIM, 1);
    const float* dt_bias0 = pick(d_in, in_sizes, n_in, NHEADS, 0);
    const float* dt_bias1 = pick(d_in, in_sizes, n_in, NHEADS, 3);
    const float* A_log0   = pick(d_in, in_sizes, n_in, NHEADS, 1);
    const float* A_log1   = pick(d_in, in_sizes, n_in, NHEADS, 4);
    const float* Dp0      = pick(d_in, in_sizes, n_in, NHEADS, 2);
    const float* Dp1      = pick(d_in, in_sizes, n_in, NHEADS, 5);
    const float* norm_w0  = pick(d_in, in_sizes, n_in, DINNER, 0);
    const float* norm_w1  = pick(d_in, in_sizes, n_in, DINNER, 1);
    const float* out_w0   = pick(d_in, in_sizes, n_in, DINNER * DMODEL, 0);
    const float* out_w1   = pick(d_in, in_sizes, n_in, DINNER * DMODEL, 1);

    __half* p_proj = 0; cudaGetSymbolAddress((void**)&p_proj, h_proj);
    __half* p_conv = 0; cudaGetSymbolAddress((void**)&p_conv, h_conv);
    float* p_dt   = 0;  cudaGetSymbolAddress((void**)&p_dt,   g_dt);
    float* p_dA   = 0;  cudaGetSymbolAddress((void**)&p_dA,   g_dA);
    __half* p_y   = 0;  cudaGetSymbolAddress((void**)&p_y,    h_y);
    float* p_h2   = 0;  cudaGetSymbolAddress((void**)&p_h2,   g_h2);

    __half* ph_xn  = 0; cudaGetSymbolAddress((void**)&ph_xn,  h_xn);
    __half* ph_yg  = 0; cudaGetSymbolAddress((void**)&ph_yg,  h_yg);
    __half* ph_bi  = 0; cudaGetSymbolAddress((void**)&ph_bi,  h_bi);
    __half* ph_ffn = 0; cudaGetSymbolAddress((void**)&ph_ffn, h_ffn);

    __half* pw_in0  = 0; cudaGetSymbolAddress((void**)&pw_in0,  hw_in0);
    __half* pw_in1  = 0; cudaGetSymbolAddress((void**)&pw_in1,  hw_in1);
    __half* pw_out0 = 0; cudaGetSymbolAddress((void**)&pw_out0, hw_out0);
    __half* pw_out1 = 0; cudaGetSymbolAddress((void**)&pw_out1, hw_out1);
    __half* pw_f1   = 0; cudaGetSymbolAddress((void**)&pw_f1,   hw_f1);
    __half* pw_f2   = 0; cudaGetSymbolAddress((void**)&pw_f2,   hw_f2);

    cudaFuncSetAttribute(hgemm_wmma<0>, cudaFuncAttributeMaxDynamicSharedMemorySize, GEMM_SMEM_BYTES);
    cudaFuncSetAttribute(hgemm_wmma<1>, cudaFuncAttributeMaxDynamicSharedMemorySize, GEMM_SMEM_BYTES);
    cudaFuncSetAttribute(hgemm_wmma<2>, cudaFuncAttributeMaxDynamicSharedMemorySize, GEMM_SMEM_BYTES);

    float* out = (float*)d_out;
    const int T = 256;

    // 1) merged weight conversion fp32 -> fp16 (single launch)
    f2h_all_kernel<<<(F2H_TOT + T - 1) / T, T>>>(
        in_w0, in_w1, out_w0, out_w1, ffn_w1, ffn_w2,
        pw_in0, pw_in1, pw_out0, pw_out1, pw_f1, pw_f2);

    // 2) LN1 -> fp16
    layernorm_kernel<<<NTOK, 256>>>(x, nullptr, nullptr, ln1_w, ln1_b, nullptr, ph_xn, 0);

    // 3) in_proj both dirs (z-batched) -> fp16 proj
    {
        dim3 grid((DPROJ + BN - 1) / BN, NTOK / BM, 2);
        hgemm_wmma<1><<<grid, TPB, GEMM_SMEM_BYTES>>>(
            ph_xn, 0, pw_in0, pw_in1, nullptr,
            nullptr, p_proj, (size_t)NTOK * DPROJP,
            NTOK, DPROJ, DMODEL, DPROJP, 0, 0);
    }
    // 4) dt/dA both dirs
    dtda_kernel<<<(2 * NTOK * NHEADS + T - 1) / T, T>>>(p_proj, dt_bias0, dt_bias1, A_log0, A_log1, p_dt, p_dA);
    // 5) conv both dirs -> fp16
    conv_kernel<<<(2 * NTOK * CONV2 + T - 1) / T, T>>>(p_proj, conv_w0, conv_w1, conv_b0, conv_b1, p_conv);
    // 6) scan both dirs (192 CTAs x 256 threads, register-dense) -> fp16 y
    scan_kernel<<<2 * BATCH * NHEADS, 256>>>(p_conv, p_dt, p_dA, Dp0, Dp1, p_y);
    // 7) gate + rmsnorm both dirs -> fp16
    gate_rmsnorm_kernel<<<2 * NTOK, 256>>>(p_proj, p_y, norm_w0, norm_w1, ph_yg);
    // 8) out_proj both dirs (z-batched) -> fp16 concat buffer
    {
        dim3 grid(DMODEL / BN, NTOK / BM, 2);
        hgemm_wmma<1><<<grid, TPB, GEMM_SMEM_BYTES>>>(
            ph_yg, (size_t)NTOK * DINNER, pw_out0, pw_out1, nullptr,
            nullptr, ph_bi, 0,
            NTOK, DMODEL, DINNER, DINNER, 0, DMODEL);
    }
    // 9) FFN1 with fused bias+gelu -> fp16
    {
        dim3 grid(DFFN / BN, NTOK / BM, 1);
        hgemm_wmma<2><<<grid, TPB, GEMM_SMEM_BYTES>>>(
            ph_bi, 0, pw_f1, pw_f1, ffn_b1,
            nullptr, ph_ffn, 0,
            NTOK, DFFN, DINNER, DFFN, 0, 0);
    }
    // 10) FFN2 -> fp32 raw
    {
        dim3 grid(DMODEL / BN, NTOK / BM, 1);
        hgemm_wmma<0><<<grid, TPB, GEMM_SMEM_BYTES>>>(
            ph_ffn, 0, pw_f2, pw_f2, nullptr,
            p_h2, nullptr, 0,
            NTOK, DMODEL, DFFN, DMODEL, 0, 0);
    }
    // 11) out = LN2(x + gelu(h2 + b2))
    layernorm_kernel<<<NTOK, 256>>>(x, p_h2, ffn_b2, ln2_w, ln2_b, out, nullptr, 1);
}

// round 15
// speedup vs baseline: 1.2652x; 1.0004x over previous
#include <cuda_runtime.h>
#include <cuda_fp16.h>
#include <cuda_pipeline.h>
#include <mma.h>
#include <math.h>

using namespace nvcuda;

// ---------------- problem constants ----------------
#define BATCH   4
#define SEQ     2048
#define DMODEL  768
#define DSTATE  16
#define DCONV   4
#define HEADDIM 64
#define DINNER  1536
#define NHEADS  24
#define CONVDIM 1568
#define DPROJ   3128
#define DPROJP  3328
#define NTOK    (BATCH*SEQ)
#define DFFN    3072

// ---------------- scratch (device globals; no allocation allowed) ----------------
__device__ __half h_proj[(size_t)2*NTOK*DPROJP];
__device__ __half h_conv[(size_t)2*NTOK*CONVDIM];
__device__ float  g_dt  [(size_t)2*NTOK*NHEADS];
__device__ float  g_dA  [(size_t)2*NTOK*NHEADS];
__device__ __half h_y   [(size_t)2*NTOK*DINNER];
__device__ __half h_yg  [(size_t)2*NTOK*DINNER];
__device__ float  g_h2  [(size_t)NTOK*DMODEL];

__device__ __half h_xn [(size_t)NTOK*DMODEL];
__device__ __half h_bi [(size_t)NTOK*DINNER];
__device__ __half h_ffn[(size_t)NTOK*DFFN];

// fp16 weight buffers
__device__ __half hw_in0 [(size_t)DMODEL*DPROJ];
__device__ __half hw_in1 [(size_t)DMODEL*DPROJ];
__device__ __half hw_out0[(size_t)DINNER*DMODEL];
__device__ __half hw_out1[(size_t)DINNER*DMODEL];
__device__ __half hw_f1  [(size_t)DINNER*DFFN];
__device__ __half hw_f2  [(size_t)DFFN*DMODEL];

// ---------------- helpers ----------------
__device__ __forceinline__ float gelu_exact(float x) {
    return 0.5f * x * (1.0f + erff(x * 0.70710678118654752f));
}
__device__ __forceinline__ float silu(float x) {
    return x / (1.0f + expf(-x));
}

__device__ float block_reduce_sum(float v) {
    __shared__ float sh[32];
    __shared__ float tot;
    int lane = threadIdx.x & 31, wid = threadIdx.x >> 5;
    #pragma unroll
    for (int m = 16; m >= 1; m >>= 1) v += __shfl_xor_sync(0xffffffffu, v, m);
    if (lane == 0) sh[wid] = v;
    __syncthreads();
    int nw = blockDim.x >> 5;
    v = (threadIdx.x < nw) ? sh[threadIdx.x] : 0.f;
    if (wid == 0) {
        #pragma unroll
        for (int m = 16; m >= 1; m >>= 1) v += __shfl_xor_sync(0xffffffffu, v, m);
        if (lane == 0) tot = v;
    }
    __syncthreads();
    return tot;
}

// ---------------- merged fp32 -> fp16 conversion for all 6 weights ----------------
#define N4_IN  (DMODEL*DPROJ/4)
#define N4_OUT (DINNER*DMODEL/4)
#define N4_F1  (DINNER*DFFN/4)
#define N4_F2  (DFFN*DMODEL/4)
#define F2H_B0 (N4_IN)
#define F2H_B1 (2*N4_IN)
#define F2H_B2 (2*N4_IN + N4_OUT)
#define F2H_B3 (2*N4_IN + 2*N4_OUT)
#define F2H_B4 (2*N4_IN + 2*N4_OUT + N4_F1)
#define F2H_TOT (2*N4_IN + 2*N4_OUT + N4_F1 + N4_F2)

__global__ void f2h_all_kernel(
    const float* __restrict__ s0, const float* __restrict__ s1,
    const float* __restrict__ s2, const float* __restrict__ s3,
    const float* __restrict__ s4, const float* __restrict__ s5,
    __half* __restrict__ d0, __half* __restrict__ d1,
    __half* __restrict__ d2, __half* __restrict__ d3,
    __half* __restrict__ d4, __half* __restrict__ d5)
{
    int i = blockIdx.x * blockDim.x + threadIdx.x;
    if (i >= F2H_TOT) return;
    const float* src;
    __half* dst;
    int j;
    if (i < F2H_B0)      { src = s0; dst = d0; j = i; }
    else if (i < F2H_B1) { src = s1; dst = d1; j = i - F2H_B0; }
    else if (i < F2H_B2) { src = s2; dst = d2; j = i - F2H_B1; }
    else if (i < F2H_B3) { src = s3; dst = d3; j = i - F2H_B2; }
    else if (i < F2H_B4) { src = s4; dst = d4; j = i - F2H_B3; }
    else                 { src = s5; dst = d5; j = i - F2H_B4; }
    float4 v = ((const float4*)src)[j];
    ((__half2*)dst)[j * 2 + 0] = __floats2half2_rn(v.x, v.y);
    ((__half2*)dst)[j * 2 + 1] = __floats2half2_rn(v.z, v.w);
}

// ---------------- layernorm (cols = 768) ----------------
__global__ __launch_bounds__(256) void layernorm_kernel(
    const float* __restrict__ x, const float* __restrict__ add,
    const float* __restrict__ addb,
    const float* __restrict__ w, const float* __restrict__ b,
    float* __restrict__ out, __half* __restrict__ outh, int mode)
{
    int row = blockIdx.x;
    int tid = threadIdx.x;
    const size_t base = (size_t)row * DMODEL;
    float v[3];
    float s = 0.f;
    #pragma unroll
    for (int i = 0; i < 3; i++) {
        int c = tid + i * 256;
        float t = x[base + c];
        if (mode == 1) t += gelu_exact(add[base + c] + addb[c]);
        v[i] = t; s += t;
    }
    float mean = block_reduce_sum(s) * (1.0f / DMODEL);
    float sq = 0.f;
    #pragma unroll
    for (int i = 0; i < 3; i++) { float d = v[i] - mean; sq += d * d; }
    float var = block_reduce_sum(sq) * (1.0f / DMODEL);
    float rstd = rsqrtf(var + 1e-5f);
    #pragma unroll
    for (int i = 0; i < 3; i++) {
        int c = tid + i * 256;
        float r = (v[i] - mean) * rstd * w[c] + b[c];
        if (out)  out[base + c] = r;
        if (outh) outh[base + c] = __float2half_rn(r);
    }
}

// ---------------- WMMA HGEMM: CTA 128x128, 4 warps of 64x64, BK=32, 3-stage ----------------
// MODE 0: fp32 raw -> Cf ; MODE 1: fp16 raw -> Ch ; MODE 2: bias+gelu -> fp16 Ch
#define BM 128
#define BN 128
#define BK 32
#define TPB 128
#define NSTAGE 3
#define ASTR 40
#define BSTR 136
#define AS_HALFS (BM * ASTR)
#define BS_HALFS (BK * BSTR)
#define STAGE_HALFS (AS_HALFS + BS_HALFS)
#define EPI_LDS 132
#define SMEM_PIPE ((size_t)(NSTAGE * STAGE_HALFS * 2))
#define SMEM_EPI  ((size_t)(BM * EPI_LDS * 4))
#define GEMM_SMEM_BYTES (SMEM_EPI > SMEM_PIPE ? SMEM_EPI : SMEM_PIPE)

__device__ __forceinline__ void hgemm_stage(
    const __half* __restrict__ A, const __half* __restrict__ W,
    int K, int N, int m0, int n0, int k0,
    __half* Asb, __half* Bsb, int tid)
{
    #pragma unroll
    for (int i = 0; i < 4; i++) {
        int c = tid + i * TPB;
        int row = c >> 2;
        int col8 = (c & 3) << 3;
        const __half* src = A + (size_t)(m0 + row) * K + k0 + col8;
        __pipeline_memcpy_async(Asb + row * ASTR + col8, src, 16);
    }
    #pragma unroll
    for (int i = 0; i < 4; i++) {
        int c = tid + i * TPB;
        int row = c >> 4;
        int col8 = (c & 15) << 3;
        __half* d = Bsb + row * BSTR + col8;
        if (n0 + col8 < N) {
            const __half* src = W + (size_t)(k0 + row) * N + n0 + col8;
            __pipeline_memcpy_async(d, src, 16);
        } else {
            *(float4*)d = make_float4(0.f, 0.f, 0.f, 0.f);
        }
    }
    __pipeline_commit();
}

template<int MODE>
__global__ __launch_bounds__(TPB) void hgemm_wmma(
    const __half* __restrict__ A, size_t aStride,
    const __half* __restrict__ W0, const __half* __restrict__ W1,
    const float* __restrict__ bias,
    float* __restrict__ Cf, __half* __restrict__ Ch, size_t outStride,
    int M, int N, int K, int ldc, int coff0, int coffStep)
{
    extern __shared__ __half smem[];

    const int tid  = threadIdx.x;
    const int wid  = tid >> 5;
    const int warp_m = wid & 1;
    const int warp_n = wid >> 1;
    const int m0 = blockIdx.y * BM;
    const int n0 = blockIdx.x * BN;
    const int z  = blockIdx.z;

    const __half* W = (z == 0) ? W0 : W1;
    A += (size_t)z * aStride;
    if (Cf) Cf += (size_t)z * outStride;
    if (Ch) Ch += (size_t)z * outStride;
    const int coff = coff0 + z * coffStep;

    wmma::fragment<wmma::accumulator, 16, 16, 16, float> cfr[4][4];
    #pragma unroll
    for (int i = 0; i < 4; i++) {
        #pragma unroll
        for (int j = 0; j < 4; j++) wmma::fill_fragment(cfr[i][j], 0.0f);
    }

    const int nK = K / BK;
    hgemm_stage(A, W, K, N, m0, n0, 0, smem, smem + AS_HALFS, tid);
    if (nK > 1) {
        __half* st = smem + STAGE_HALFS;
        hgemm_stage(A, W, K, N, m0, n0, BK, st, st + AS_HALFS, tid);
    }

    for (int kt = 0; kt < nK; kt++) {
        __pipeline_wait_prior(NSTAGE - 2);
        __syncthreads();
        if (kt + 2 < nK) {
            __half* st = smem + ((kt + 2) % NSTAGE) * STAGE_HALFS;
            hgemm_stage(A, W, K, N, m0, n0, (kt + 2) * BK, st, st + AS_HALFS, tid);
        }
        const __half* As = smem + (kt % NSTAGE) * STAGE_HALFS;
        const __half* Bs = As + AS_HALFS;

        #pragma unroll
        for (int kc = 0; kc < BK; kc += 16) {
            wmma::fragment<wmma::matrix_a, 16, 16, 16, __half, wmma::row_major> afr[4];
            wmma::fragment<wmma::matrix_b, 16, 16, 16, __half, wmma::row_major> bfr[4];
            #pragma unroll
            for (int i = 0; i < 4; i++) {
                wmma::load_matrix_sync(afr[i], As + (warp_m * 64 + i * 16) * ASTR + kc, ASTR);
            }
            #pragma unroll
            for (int j = 0; j < 4; j++) {
                wmma::load_matrix_sync(bfr[j], Bs + kc * BSTR + warp_n * 64 + j * 16, BSTR);
            }
            #pragma unroll
            for (int i = 0; i < 4; i++) {
                #pragma unroll
                for (int j = 0; j < 4; j++) {
                    wmma::mma_sync(cfr[i][j], afr[i], bfr[j], cfr[i][j]);
                }
            }
        }
    }

    if (MODE == 2) {
        __syncthreads();
        float* stg = (float*)smem;
        #pragma unroll
        for (int i = 0; i < 4; i++) {
            #pragma unroll
            for (int j = 0; j < 4; j++) {
                wmma::store_matrix_sync(stg + (warp_m * 64 + i * 16) * EPI_LDS + warp_n * 64 + j * 16,
                                        cfr[i][j], EPI_LDS, wmma::mem_row_major);
            }
        }
        __syncthreads();
        #pragma unroll
        for (int it = 0; it < 32; it++) {
            int q = tid + it * TPB;
            int r  = q >> 5;
            int c4 = (q & 31) << 2;
            int colb = n0 + c4;
            if (colb >= N) continue;
            float4 v = *(const float4*)(stg + r * EPI_LDS + c4);
            float r0 = gelu_exact(v.x + bias[colb + 0]);
            float r1 = gelu_exact(v.y + bias[colb + 1]);
            float r2 = gelu_exact(v.z + bias[colb + 2]);
            float r3 = gelu_exact(v.w + bias[colb + 3]);
            __half* dst = Ch + (size_t)(m0 + r) * ldc + coff + colb;
            ((__half2*)dst)[0] = __floats2half2_rn(r0, r1);
            ((__half2*)dst)[1] = __floats2half2_rn(r2, r3);
        }
    } else {
        #pragma unroll
        for (int i = 0; i < 4; i++) {
            #pragma unroll
            for (int j = 0; j < 4; j++) {
                int row = m0 + warp_m * 64 + i * 16;
                int col = n0 + warp_n * 64 + j * 16;
                if (MODE == 1) {
                    wmma::fragment<wmma::accumulator, 16, 16, 16, __half> hf;
                    #pragma unroll
                    for (int t = 0; t < hf.num_elements; t++) {
                        hf.x[t] = __float2half_rn(cfr[i][j].x[t]);
                    }
                    wmma::store_matrix_sync(Ch + (size_t)row * ldc + coff + col, hf, ldc, wmma::mem_row_major);
                } else {
                    wmma::store_matrix_sync(Cf + (size_t)row * ldc + coff + col, cfr[i][j], ldc, wmma::mem_row_major);
                }
            }
        }
    }
}

// ---------------- dt / dA (both directions) ----------------
__global__ void dtda_kernel(const __half* __restrict__ proj,
                            const float* __restrict__ dtb0, const float* __restrict__ dtb1,
                            const float* __restrict__ al0,  const float* __restrict__ al1,
                            float* __restrict__ dt, float* __restrict__ dA)
{
    int idx = blockIdx.x * blockDim.x + threadIdx.x;
    if (idx >= 2 * NTOK * NHEADS) return;
    int dir = idx / (NTOK * NHEADS);
    int rem = idx - dir * (NTOK * NHEADS);
    int h = rem % NHEADS;
    int j = rem / NHEADS;
    const float* dtb = dir ? dtb1 : dtb0;
    const float* al  = dir ? al1  : al0;
    float pv = __half2float(proj[(size_t)dir * NTOK * DPROJP + (size_t)j * DPROJP + (DINNER + CONVDIM) + h]);
    float raw = pv + dtb[h];
    float d = (raw > 20.f) ? raw : log1pf(expf(raw));
    float A = -expf(al[h]);
    dt[idx] = d;
    dA[idx] = expf(d * A);
}

// ---------------- depthwise conv + silu, 2 channels/thread -> fp16 ----------------
#define CONV2 (CONVDIM/2)
__global__ void conv_kernel(const __half* __restrict__ proj,
                            const float* __restrict__ cw0, const float* __restrict__ cw1,
                            const float* __restrict__ cb0, const float* __restrict__ cb1,
                            __half* __restrict__ out)
{
    int idx = blockIdx.x * blockDim.x + threadIdx.x;
    if (idx >= 2 * NTOK * CONV2) return;
    int dir = idx / (NTOK * CONV2);
    int rem = idx - dir * (NTOK * CONV2);
    int c2 = rem % CONV2;
    int row = rem / CONV2;
    int t = row % SEQ;
    int brow = row - t;
    int c = c2 * 2;
    const float* cw = dir ? cw1 : cw0;
    const float* cb = dir ? cb1 : cb0;
    const __half* pb = proj + (size_t)dir * NTOK * DPROJP;
    float acc0 = cb[c], acc1 = cb[c + 1];
    #pragma unroll
    for (int k = 0; k < DCONV; k++) {
        int tt = dir ? (t + (DCONV - 1) - k) : (t + k - (DCONV - 1));
        if (tt >= 0 && tt < SEQ) {
            __half2 pv = *(const __half2*)(pb + (size_t)(brow + tt) * DPROJP + DINNER + c);
            float2 p = __half22float2(pv);
            acc0 += cw[c * DCONV + k] * p.x;
            acc1 += cw[(c + 1) * DCONV + k] * p.y;
        }
    }
    __half2* ob = (__half2*)(out + (size_t)dir * NTOK * CONVDIM + (size_t)row * CONVDIM);
    ob[c2] = __floats2half2_rn(silu(acc0), silu(acc1));
}

// ---------------- selective scan: register-dense, 4 n-states/thread ----------------
// 256 threads per (dir,b,h). Thread layout: warp w handles p in [w*8, w*8+8);
// lane = ngroup*8 + (p&7); each thread owns n-states [ngroup*4, ngroup*4+4).
#define SCHUNK 64
__global__ __launch_bounds__(256) void scan_kernel(
    const __half* __restrict__ conv, const float* __restrict__ dt,
    const float* __restrict__ dA,
    const float* __restrict__ Dp0, const float* __restrict__ Dp1,
    __half* __restrict__ y)
{
    int unit = blockIdx.x;
    int dir = unit / (BATCH * NHEADS);
    int rem = unit - dir * (BATCH * NHEADS);
    int b = rem / NHEADS;
    int h = rem % NHEADS;
    int tid = threadIdx.x;
    int w = tid >> 5, lane = tid & 31;
    int p  = w * 8 + (lane & 7);
    int ng = lane >> 3;
    int n0 = ng * 4;
    int reverse = dir;

    const __half* convb = conv + (size_t)dir * NTOK * CONVDIM;
    const float* dtb   = dt   + (size_t)dir * NTOK * NHEADS;
    const float* dAb   = dA   + (size_t)dir * NTOK * NHEADS;
    __half* yb         = y    + (size_t)dir * NTOK * DINNER;
    const float Dv = dir ? Dp1[h] : Dp0[h];

    __shared__ __half sx[SCHUNK][HEADDIM];
    __shared__ float sB[SCHUNK][DSTATE];
    __shared__ float sC[SCHUNK][DSTATE];
    __shared__ float sdt[SCHUNK];
    __shared__ float sdA[SCHUNK];

    float hs0 = 0.f, hs1 = 0.f, hs2 = 0.f, hs3 = 0.f;

    for (int c0 = 0; c0 < SEQ; c0 += SCHUNK) {
        // x tile: 64 rows x 64 halves = 512 uint4 chunks; 256 threads x 2
        #pragma unroll
        for (int i = 0; i < 2; i++) {
            int q = tid + i * 256;
            int s = q >> 3, o = (q & 7) * 8;
            int t = reverse ? (SEQ - 1 - (c0 + s)) : (c0 + s);
            *(uint4*)&sx[s][o] = *(const uint4*)(convb + (size_t)(b * SEQ + t) * CONVDIM + h * HEADDIM + o);
        }
        // B+C tile: 64 rows x 32 halves (contiguous at DINNER) = 256 uint4; 1 per thread
        {
            int s = tid >> 2, o = (tid & 3) * 8;
            int t = reverse ? (SEQ - 1 - (c0 + s)) : (c0 + s);
            const __half* src = convb + (size_t)(b * SEQ + t) * CONVDIM + DINNER + o;
            #pragma unroll
            for (int k = 0; k < 8; k++) {
                float v = __half2float(src[k]);
                int idx = o + k;
                if (idx < DSTATE) sB[s][idx] = v;
                else              sC[s][idx - DSTATE] = v;
            }
        }
        if (tid < SCHUNK) {
            int t = reverse ? (SEQ - 1 - (c0 + tid)) : (c0 + tid);
            sdt[tid] = dtb[(size_t)(b * SEQ + t) * NHEADS + h];
            sdA[tid] = dAb[(size_t)(b * SEQ + t) * NHEADS + h];
        }
        __syncthreads();

        #pragma unroll 4
        for (int s = 0; s < SCHUNK; s++) {
            float dAv = sdA[s], dtv = sdt[s];
            float x = __half2float(sx[s][p]);
            float dtx = dtv * x;
            float4 B4 = *(const float4*)&sB[s][n0];
            float4 C4 = *(const float4*)&sC[s][n0];
            hs0 = hs0 * dAv + dtx * B4.x;
            hs1 = hs1 * dAv + dtx * B4.y;
            hs2 = hs2 * dAv + dtx * B4.z;
            hs3 = hs3 * dAv + dtx * B4.w;
            float yv = hs0 * C4.x + hs1 * C4.y + hs2 * C4.z + hs3 * C4.w;
            yv += __shfl_xor_sync(0xffffffffu, yv, 8);
            yv += __shfl_xor_sync(0xffffffffu, yv, 16);
            if (ng == 0) {
                int t = reverse ? (SEQ - 1 - (c0 + s)) : (c0 + s);
                yb[(size_t)(b * SEQ + t) * DINNER + h * HEADDIM + p] = __float2half_rn(yv + Dv * x);
            }
        }
        __syncthreads();
    }
}

// ---------------- gate (y * silu(z)) + grouped RMSNorm -> fp16 (both dirs) ----------------
__global__ __launch_bounds__(256) void gate_rmsnorm_kernel(
    const __half* __restrict__ proj, const __half* __restrict__ y_in,
    const float* __restrict__ nw0, const float* __restrict__ nw1,
    __half* __restrict__ y_out)
{
    int dir = blockIdx.x >> 13;
    int row = blockIdx.x & (NTOK - 1);
    int tid = threadIdx.x;
    const __half2* pb = (const __half2*)(proj + (size_t)dir * NTOK * DPROJP + (size_t)row * DPROJP);
    const __half2* yb = (const __half2*)(y_in + (size_t)dir * NTOK * DINNER + (size_t)row * DINNER);
    __half2* ob       = (__half2*)(y_out + (size_t)dir * NTOK * DINNER + (size_t)row * DINNER);
    const float* nw  = dir ? nw1 : nw0;

    float v[6];
    float ss = 0.f;
    #pragma unroll
    for (int i = 0; i < 3; i++) {
        int c2 = tid + i * 256;          // half2 index over 768
        float2 z  = __half22float2(pb[c2]);
        float2 yv = __half22float2(yb[c2]);
        float t0 = yv.x * silu(z.x);
        float t1 = yv.y * silu(z.y);
        v[i * 2 + 0] = t0; v[i * 2 + 1] = t1;
        ss += t0 * t0 + t1 * t1;
    }
    float tot = block_reduce_sum(ss);
    float rs = rsqrtf(tot * (1.0f / DINNER) + 1e-5f);
    #pragma unroll
    for (int i = 0; i < 3; i++) {
        int c2 = tid + i * 256;
        float r0 = v[i * 2 + 0] * rs * nw[c2 * 2 + 0];
        float r1 = v[i * 2 + 1] * rs * nw[c2 * 2 + 1];
        ob[c2] = __floats2half2_rn(r0, r1);
    }
}

// ---------------- host-side input binding by element count ----------------
static const float* pick(void* const* d_in, const int* sz, int n_in, int count, int occ) {
    int seen = 0;
    for (int i = 0; i < n_in; i++) {
        if (sz[i] == count) {
            if (seen == occ) return (const float*)d_in[i];
            seen++;
        }
    }
    return nullptr;
}

extern "C" void kernel_launch(void* const* d_in, const int* in_sizes, int n_in,
                              void* d_out, int out_size)
{
    const float* x      = pick(d_in, in_sizes, n_in, NTOK * DMODEL, 0);
    const float* ln1_w  = pick(d_in, in_sizes, n_in, 768, 0);
    const float* ln1_b  = pick(d_in, in_sizes, n_in, 768, 1);
    const float* ln2_w  = pick(d_in, in_sizes, n_in, 768, 2);
    const float* ln2_b  = pick(d_in, in_sizes, n_in, 768, 3);
    const float* ffn_b2 = pick(d_in, in_sizes, n_in, 768, 4);
    const float* ffn_w1 = pick(d_in, in_sizes, n_in, DINNER * DFFN, 0);
    const float* ffn_b1 = pick(d_in, in_sizes, n_in, DFFN, 0);
    const float* ffn_w2 = pick(d_in, in_sizes, n_in, DFFN * DMODEL, 0);

    const float* in_w0    = pick(d_in, in_sizes, n_in, DMODEL * DPROJ, 0);
    const float* in_w1    = pick(d_in, in_sizes, n_in, DMODEL * DPROJ, 1);
    const float* conv_w0  = pick(d_in, in_sizes, n_in, CONVDIM * DCONV, 0);
    const float* conv_w1  = pick(d_in, in_sizes, n_in, CONVDIM * DCONV, 1);
    const float* conv_b0  = pick(d_in, in_sizes, n_in, CONVDIM, 0);
    const float* conv_b1  = pick(d_in, in_sizes, n_in, CONVDIM, 1);
    const float* dt_bias0 = pick(d_in, in_sizes, n_in, NHEADS, 0);
    const float* dt_bias1 = pick(d_in, in_sizes, n_in, NHEADS, 3);
    const float* A_log0   = pick(d_in, in_sizes, n_in, NHEADS, 1);
    const float* A_log1   = pick(d_in, in_sizes, n_in, NHEADS, 4);
    const float* Dp0      = pick(d_in, in_sizes, n_in, NHEADS, 2);
    const float* Dp1      = pick(d_in, in_sizes, n_in, NHEADS, 5);
    const float* norm_w0  = pick(d_in, in_sizes, n_in, DINNER, 0);
    const float* norm_w1  = pick(d_in, in_sizes, n_in, DINNER, 1);
    const float* out_w0   = pick(d_in, in_sizes, n_in, DINNER * DMODEL, 0);
    const float* out_w1   = pick(d_in, in_sizes, n_in, DINNER * DMODEL, 1);

    __half* p_proj = 0; cudaGetSymbolAddress((void**)&p_proj, h_proj);
    __half* p_conv = 0; cudaGetSymbolAddress((void**)&p_conv, h_conv);
    float* p_dt   = 0;  cudaGetSymbolAddress((void**)&p_dt,   g_dt);
    float* p_dA   = 0;  cudaGetSymbolAddress((void**)&p_dA,   g_dA);
    __half* p_y   = 0;  cudaGetSymbolAddress((void**)&p_y,    h_y);
    float* p_h2   = 0;  cudaGetSymbolAddress((void**)&p_h2,   g_h2);

    __half* ph_xn  = 0; cudaGetSymbolAddress((void**)&ph_xn,  h_xn);
    __half* ph_yg  = 0; cudaGetSymbolAddress((void**)&ph_yg,  h_yg);
    __half* ph_bi  = 0; cudaGetSymbolAddress((void**)&ph_bi,  h_bi);
    __half* ph_ffn = 0; cudaGetSymbolAddress((void**)&ph_ffn, h_ffn);

    __half* pw_in0  = 0; cudaGetSymbolAddress((void**)&pw_in0,  hw_in0);
    __half* pw_in1  = 0; cudaGetSymbolAddress((void**)&pw_in1,  hw_in1);
    __half* pw_out0 = 0; cudaGetSymbolAddress((void**)&pw_out0, hw_out0);
    __half* pw_out1 = 0; cudaGetSymbolAddress((void**)&pw_out1, hw_out1);
    __half* pw_f1   = 0; cudaGetSymbolAddress((void**)&pw_f1,   hw_f1);
    __half* pw_f2   = 0; cudaGetSymbolAddress((void**)&pw_f2,   hw_f2);

    cudaFuncSetAttribute(hgemm_wmma<0>, cudaFuncAttributeMaxDynamicSharedMemorySize, GEMM_SMEM_BYTES);
    cudaFuncSetAttribute(hgemm_wmma<1>, cudaFuncAttributeMaxDynamicSharedMemorySize, GEMM_SMEM_BYTES);
    cudaFuncSetAttribute(hgemm_wmma<2>, cudaFuncAttributeMaxDynamicSharedMemorySize, GEMM_SMEM_BYTES);

    float* out = (float*)d_out;
    const int T = 256;

    // 1) merged weight conversion fp32 -> fp16 (single launch)
    f2h_all_kernel<<<(F2H_TOT + T - 1) / T, T>>>(
        in_w0, in_w1, out_w0, out_w1, ffn_w1, ffn_w2,
        pw_in0, pw_in1, pw_out0, pw_out1, pw_f1, pw_f2);

    // 2) LN1 -> fp16
    layernorm_kernel<<<NTOK, 256>>>(x, nullptr, nullptr, ln1_w, ln1_b, nullptr, ph_xn, 0);

    // 3) in_proj both dirs (z-batched) -> fp16 proj
    {
        dim3 grid((DPROJ + BN - 1) / BN, NTOK / BM, 2);
        hgemm_wmma<1><<<grid, TPB, GEMM_SMEM_BYTES>>>(
            ph_xn, 0, pw_in0, pw_in1, nullptr,
            nullptr, p_proj, (size_t)NTOK * DPROJP,
            NTOK, DPROJ, DMODEL, DPROJP, 0, 0);
    }
    // 4) dt/dA both dirs
    dtda_kernel<<<(2 * NTOK * NHEADS + T - 1) / T, T>>>(p_proj, dt_bias0, dt_bias1, A_log0, A_log1, p_dt, p_dA);
    // 5) conv both dirs -> fp16
    conv_kernel<<<(2 * NTOK * CONV2 + T - 1) / T, T>>>(p_proj, conv_w0, conv_w1, conv_b0, conv_b1, p_conv);
    // 6) scan both dirs (192 CTAs x 256 threads, register-dense) -> fp16 y
    scan_kernel<<<2 * BATCH * NHEADS, 256>>>(p_conv, p_dt, p_dA, Dp0, Dp1, p_y);
    // 7) gate + rmsnorm both dirs -> fp16
    gate_rmsnorm_kernel<<<2 * NTOK, 256>>>(p_proj, p_y, norm_w0, norm_w1, ph_yg);
    // 8) out_proj both dirs (z-batched) -> fp16 concat buffer
    {
        dim3 grid(DMODEL / BN, NTOK / BM, 2);
        hgemm_wmma<1><<<grid, TPB, GEMM_SMEM_BYTES>>>(
            ph_yg, (size_t)NTOK * DINNER, pw_out0, pw_out1, nullptr,
            nullptr, ph_bi, 0,
            NTOK, DMODEL, DINNER, DINNER, 0, DMODEL);
    }
    // 9) FFN1 with fused bias+gelu -> fp16
    {
        dim3 grid(DFFN / BN, NTOK / BM, 1);
        hgemm_wmma<2><<<grid, TPB, GEMM_SMEM_BYTES>>>(
            ph_bi, 0, pw_f1, pw_f1, ffn_b1,
            nullptr, ph_ffn, 0,
            NTOK, DFFN, DINNER, DFFN, 0, 0);
    }
    // 10) FFN2 -> fp32 raw
    {
        dim3 grid(DMODEL / BN, NTOK / BM, 1);
        hgemm_wmma<0><<<grid, TPB, GEMM_SMEM_BYTES>>>(
            ph_ffn, 0, pw_f2, pw_f2, nullptr,
            p_h2, nullptr, 0,
            NTOK, DMODEL, DFFN, DMODEL, 0, 0);
    }
    // 11) out = LN2(x + gelu(h2 + b2))
    layernorm_kernel<<<NTOK, 256>>>(x, p_h2, ffn_b2, ln2_w, ln2_b, out, nullptr, 1);
}